// round 13
// baseline (speedup 1.0000x reference)
#include <cuda_runtime.h>
#include <cuda_bf16.h>
#include <math.h>
#include <stdint.h>

#define Bq 4
#define Tt 12
#define Pp 196
#define Dd 512
#define Hh 8
#define DHd 64
#define EPSV 1e-6f

#define M1 (Bq*Tt*Pp)            // 9408
#define ROWS_AV (Bq*Tt*Tt*Pp)    // 112896
#define POSMOD (Tt*Tt*Pp)        // 28224

#define OQ 0
#define OKo 262144
#define OV  524288
#define OT  786432
#define O1  3932160
#define O2  4456448
#define WTOT 4980736

// ---------------- scratch ----------------
__device__ float g_av[(size_t)ROWS_AV*Dd];
__device__ float g_xres[M1*Dd];
__device__ float g_btsum[Dd];
__device__ float g_bqkv[3*Dd];
__device__ __nv_bfloat16 g_x2h[M1*Dd],  g_x2l[M1*Dd];
__device__ __nv_bfloat16 g_qh[M1*Dd], g_ql[M1*Dd];
__device__ __nv_bfloat16 g_kh[M1*Dd], g_kl[M1*Dd];
__device__ __nv_bfloat16 g_vh[M1*Dd], g_vl[M1*Dd];
__device__ __nv_bfloat16 g_yh[(size_t)ROWS_AV*Dd], g_yl[(size_t)ROWS_AV*Dd];
__device__ __nv_bfloat16 g_hh[M1*2*Dd], g_hl[M1*2*Dd];
__device__ __nv_bfloat16 w_hi[WTOT], w_lo[WTOT];

// ---------------- helpers ----------------
__device__ __forceinline__ float gelu_exact(float x) {
    return 0.5f * x * (1.0f + erff(x * 0.70710678118654752f));
}
__device__ __forceinline__ uint32_t smem_u32(const void* p) {
    uint32_t a;
    asm("{ .reg .u64 t; cvta.to.shared.u64 t, %1; cvt.u32.u64 %0, t; }" : "=r"(a) : "l"(p));
    return a;
}
__device__ __forceinline__ void ldsm4(uint32_t* r, uint32_t a) {
    asm volatile("ldmatrix.sync.aligned.m8n8.x4.shared.b16 {%0,%1,%2,%3}, [%4];"
                 : "=r"(r[0]), "=r"(r[1]), "=r"(r[2]), "=r"(r[3]) : "r"(a));
}
__device__ __forceinline__ void ldsm4t(uint32_t* r, uint32_t a) {
    asm volatile("ldmatrix.sync.aligned.m8n8.x4.trans.shared.b16 {%0,%1,%2,%3}, [%4];"
                 : "=r"(r[0]), "=r"(r[1]), "=r"(r[2]), "=r"(r[3]) : "r"(a));
}
__device__ __forceinline__ void mma_bf16(float* c, const uint32_t* a, uint32_t b0, uint32_t b1) {
    asm volatile(
        "mma.sync.aligned.m16n8k16.row.col.f32.bf16.bf16.f32 "
        "{%0,%1,%2,%3}, {%4,%5,%6,%7}, {%8,%9}, {%0,%1,%2,%3};"
        : "+f"(c[0]), "+f"(c[1]), "+f"(c[2]), "+f"(c[3])
        : "r"(a[0]), "r"(a[1]), "r"(a[2]), "r"(a[3]), "r"(b0), "r"(b1));
}
__device__ __forceinline__ void cpa16(uint32_t s, const void* g) {
    asm volatile("cp.async.cg.shared.global [%0], [%1], 16;" :: "r"(s), "l"(g));
}
#define CPA_COMMIT() asm volatile("cp.async.commit_group;" ::: "memory")
#define CPA_WAIT(n)  asm volatile("cp.async.wait_group %0;" :: "n"(n) : "memory")

__device__ __forceinline__ uint32_t pack_bf16(float a, float b) {
    __nv_bfloat162 t = __floats2bfloat162_rn(a, b);
    return *(uint32_t*)&t;
}
__device__ __forceinline__ void split_store(__nv_bfloat16* hi, __nv_bfloat16* lo,
                                            size_t i, float v) {
    __nv_bfloat16 h = __float2bfloat16(v);
    hi[i] = h;
    lo[i] = __float2bfloat16(v - __bfloat162float(h));
}

// ---------------- LN row body (warp-per-row) ----------------
__device__ __forceinline__ void ln_row(const float* __restrict__ in,
                                       const float* __restrict__ al,
                                       const float* __restrict__ be,
                                       const float* __restrict__ pos,
                                       __nv_bfloat16* __restrict__ oh,
                                       __nv_bfloat16* __restrict__ ol,
                                       int posmod, int row, int lane) {
    const float* rp = in + (size_t)row * Dd;
    float4 v[4];
    float s = 0.f, sq = 0.f;
    #pragma unroll
    for (int j = 0; j < 4; j++) {
        v[j] = *(const float4*)&rp[lane * 4 + j * 128];
        s  += v[j].x + v[j].y + v[j].z + v[j].w;
        sq += v[j].x*v[j].x + v[j].y*v[j].y + v[j].z*v[j].z + v[j].w*v[j].w;
    }
    #pragma unroll
    for (int o = 16; o; o >>= 1) {
        s  += __shfl_xor_sync(0xffffffffu, s,  o);
        sq += __shfl_xor_sync(0xffffffffu, sq, o);
    }
    float mu  = s * (1.0f / Dd);
    float var = (sq - (float)Dd * mu * mu) * (1.0f / (Dd - 1));
    float inv = 1.0f / (sqrtf(fmaxf(var, 0.f)) + EPSV);
    const float* pp = pos ? (pos + (size_t)(row % posmod) * Dd) : nullptr;

    #pragma unroll
    for (int j = 0; j < 4; j++) {
        int c = lane * 4 + j * 128;
        float4 a = *(const float4*)&al[c];
        float4 b = *(const float4*)&be[c];
        float o0 = a.x * (v[j].x - mu) * inv + b.x;
        float o1 = a.y * (v[j].y - mu) * inv + b.y;
        float o2 = a.z * (v[j].z - mu) * inv + b.z;
        float o3 = a.w * (v[j].w - mu) * inv + b.w;
        if (pp) {
            float4 p = *(const float4*)&pp[c];
            o0 += p.x; o1 += p.y; o2 += p.z; o3 += p.w;
        }
        __nv_bfloat16 h0 = __float2bfloat16(o0);
        __nv_bfloat16 h1 = __float2bfloat16(o1);
        __nv_bfloat16 h2 = __float2bfloat16(o2);
        __nv_bfloat16 h3 = __float2bfloat16(o3);
        uint2 hv, lv;
        __nv_bfloat162 hh01 = __nv_bfloat162(h0, h1);
        __nv_bfloat162 hh23 = __nv_bfloat162(h2, h3);
        hv.x = *(uint32_t*)&hh01;
        hv.y = *(uint32_t*)&hh23;
        __nv_bfloat162 ll01 = __floats2bfloat162_rn(o0 - __bfloat162float(h0),
                                                    o1 - __bfloat162float(h1));
        __nv_bfloat162 ll23 = __floats2bfloat162_rn(o2 - __bfloat162float(h2),
                                                    o3 - __bfloat162float(h3));
        lv.x = *(uint32_t*)&ll01;
        lv.y = *(uint32_t*)&ll23;
        *(uint2*)&oh[(size_t)row * Dd + c] = hv;
        *(uint2*)&ol[(size_t)row * Dd + c] = lv;
    }
}

// ---------------- LayerNorm standalone ----------------
__global__ void ln_bf_k(const float* __restrict__ in,
                        const float* __restrict__ al,
                        const float* __restrict__ be,
                        const float* __restrict__ pos,
                        __nv_bfloat16* __restrict__ oh,
                        __nv_bfloat16* __restrict__ ol,
                        int posmod) {
    int w = threadIdx.x >> 5, lane = threadIdx.x & 31;
    ln_row(in, al, be, pos, oh, ol, posmod, blockIdx.x * 8 + w, lane);
}

// ---------------- pre1: LN(x) + QKV weight/bias convert ----------------
// blocks [0,1176): LN(x); [1176,4248): QKV wcvt + bias
__global__ void pre1_k(const float* __restrict__ x,
                       const float* __restrict__ in_a, const float* __restrict__ in_b,
                       const float* __restrict__ Wq, const float* __restrict__ Wk,
                       const float* __restrict__ Wv,
                       const float* __restrict__ bq, const float* __restrict__ bk,
                       const float* __restrict__ bv) {
    int bid = blockIdx.x, tid = threadIdx.x;
    if (bid < 1176) {
        int w = tid >> 5, lane = tid & 31;
        ln_row(x, in_a, in_b, nullptr, g_x2h, g_x2l, 1, bid * 8 + w, lane);
    } else {
        int i = (bid - 1176) * 256 + tid;
        if (i < 3 * Dd)
            g_bqkv[i] = (i < Dd) ? bq[i] : (i < 2 * Dd) ? bk[i - Dd] : bv[i - 2 * Dd];
        if (i < 786432) {
            int seg = i >> 18, off = i & 262143;
            float v = (seg == 0) ? Wq[off] : (seg == 1) ? Wk[off] : Wv[off];
            split_store(w_hi, w_lo, i, v);
        }
    }
}

// ---------------- pre2: Wt/W1/W2 convert + btsum (after attention) ----------
__global__ void pre2_k(const float* __restrict__ Wt, const float* __restrict__ W1,
                       const float* __restrict__ W2, const float* __restrict__ bt) {
    int bid = blockIdx.x, tid = threadIdx.x;
    if (bid < 16384) {
        int i = bid * 256 + tid;  // < 4194304
        float v; int di;
        if (i < 3145728)      { v = Wt[i];            di = OT + i; }
        else if (i < 3670016) { v = W1[i - 3145728];  di = O1 + (i - 3145728); }
        else                  { v = W2[i - 3670016];  di = O2 + (i - 3670016); }
        split_store(w_hi, w_lo, di, v);
    } else {
        int e = (bid - 16384) * 256 + tid;
        if (e < Dd) {
            float s = 0.f;
            #pragma unroll
            for (int u = 0; u < Tt; u++) s += bt[u * Dd + e];
            g_btsum[e] = s;
        }
    }
}

// ================= mma.sync bf16x3 GEMM v2: 2 blocks/SM ======================
// mode 1 uses a 1D grid (296) with L2-friendly block swizzle:
// groups of 8 M-rows x 4 N-cols so each A tile's 3 re-reads hit L2.
#define LDP 80
#define TILE_B (128*LDP)
#define STAGE_B (4*TILE_B)
#define GM_SMEM (2*STAGE_B)

__global__ void __launch_bounds__(256, 2) gemm_mma_k(
    const __nv_bfloat16* __restrict__ Ahi, const __nv_bfloat16* __restrict__ Alo,
    const __nv_bfloat16* __restrict__ Bhi, const __nv_bfloat16* __restrict__ Blo,
    const float* __restrict__ bias, const float* __restrict__ res,
    float* __restrict__ Cf, __nv_bfloat16* __restrict__ Chi, __nv_bfloat16* __restrict__ Clo,
    int M, int N, int K, int mode)
{
    extern __shared__ char smc[];
    int tid = threadIdx.x;
    int wid = tid >> 5, lane = tid & 31;
    int bm, bn;
    if (mode == 1) {
        int bid2 = blockIdx.x;        // 0..295
        int g = bid2 >> 5, r = bid2 & 31;
        int bmi, bni;
        if (g < 9) { bmi = g * 8 + (r & 7); bni = r >> 3; }
        else       { bmi = 72 + (r & 1);    bni = r >> 1; }
        bm = bmi * 128; bn = bni * 128;
    } else {
        bm = blockIdx.y * 128; bn = blockIdx.x * 128;
    }
    int wm = (wid >> 2) * 64;
    int wn = (wid & 3) * 32;

    int lrow = tid >> 1;
    int lhalf = tid & 1;
    int am = min(bm + lrow, M - 1);
    size_t abase;
    if (mode == 1) {
        int b_ = am / (Tt * Pp), r_ = am % (Tt * Pp);
        int t_ = r_ / Pp, p_ = r_ % Pp;
        abase = ((size_t)(b_ * (Tt * Tt) + t_ * Tt) * Pp + p_) * Dd;
    } else {
        abase = (size_t)am * K;
    }
    int brow = bn + lrow;
    uint32_t smrow = lrow * LDP;

    int NC = K / 32;

    auto load_stage = [&](int buf, int c) {
        size_t aoff, boff;
        if (mode == 1) {
            int u = c >> 4, d0 = (c & 15) * 32;
            aoff = abase + (size_t)u * (Pp * Dd) + d0;
            boff = (size_t)u * (Dd * Dd) + (size_t)brow * Dd + d0;
        } else {
            aoff = abase + c * 32;
            boff = (size_t)brow * K + c * 32;
        }
        uint32_t sb = smem_u32(smc) + buf * STAGE_B + smrow;
        #pragma unroll
        for (int i = 0; i < 2; i++) {
            int colk = lhalf * 16 + i * 8;
            uint32_t so = sb + colk * 2;
            cpa16(so,              Ahi + aoff + colk);
            cpa16(so + TILE_B,     Alo + aoff + colk);
            cpa16(so + 2*TILE_B,   Bhi + boff + colk);
            cpa16(so + 3*TILE_B,   Blo + boff + colk);
        }
    };

    int sel = lane >> 3, lr = lane & 7;
    int a_m = wm + (sel & 1) * 8 + lr;
    int b_n = wn + (sel >> 1) * 8 + lr;
    uint32_t smb = smem_u32(smc);
    uint32_t aoffB = a_m * LDP + (sel >> 1) * 16;
    uint32_t boffB = b_n * LDP + (sel & 1) * 16;

    float acc[4][4][4] = {};

    load_stage(0, 0);
    CPA_COMMIT();

    for (int c = 0; c < NC; c++) {
        int buf = c & 1;
        if (c + 1 < NC) {
            load_stage(buf ^ 1, c + 1);
            CPA_COMMIT();
            CPA_WAIT(1);
        } else {
            CPA_WAIT(0);
        }
        __syncthreads();

        uint32_t base = smb + buf * STAGE_B;
        uint32_t aHb = base + aoffB;
        uint32_t aLb = aHb + TILE_B;
        uint32_t bHb = base + 2*TILE_B + boffB;
        uint32_t bLb = bHb + TILE_B;

        #pragma unroll
        for (int kk = 0; kk < 2; kk++) {
            uint32_t ko = kk * 32;
            uint32_t bH[2][4], bL[2][4];
            #pragma unroll
            for (int nt2 = 0; nt2 < 2; nt2++) {
                ldsm4(bH[nt2], bHb + nt2 * (16 * LDP) + ko);
                ldsm4(bL[nt2], bLb + nt2 * (16 * LDP) + ko);
            }
            #pragma unroll
            for (int mt = 0; mt < 4; mt++) {
                uint32_t aH[4], aL[4];
                ldsm4(aH, aHb + mt * (16 * LDP) + ko);
                ldsm4(aL, aLb + mt * (16 * LDP) + ko);
                #pragma unroll
                for (int nt = 0; nt < 4; nt++) {
                    int s2 = nt >> 1, pp = (nt & 1) * 2;
                    mma_bf16(acc[mt][nt], aH, bH[s2][pp], bH[s2][pp+1]);
                }
                #pragma unroll
                for (int nt = 0; nt < 4; nt++) {
                    int s2 = nt >> 1, pp = (nt & 1) * 2;
                    mma_bf16(acc[mt][nt], aH, bL[s2][pp], bL[s2][pp+1]);
                }
                #pragma unroll
                for (int nt = 0; nt < 4; nt++) {
                    int s2 = nt >> 1, pp = (nt & 1) * 2;
                    mma_bf16(acc[mt][nt], aL, bH[s2][pp], bH[s2][pp+1]);
                }
            }
        }
        __syncthreads();
    }

    int qrow = lane >> 2;
    int qcol = (lane & 3) * 2;
    #pragma unroll
    for (int mt = 0; mt < 4; mt++) {
        #pragma unroll
        for (int nt = 0; nt < 4; nt++) {
            float* cc = acc[mt][nt];
            int n0 = bn + wn + nt * 8 + qcol;
            float b0 = bias[n0], b1 = bias[n0 + 1];
            #pragma unroll
            for (int hrow = 0; hrow < 2; hrow++) {
                int m = bm + wm + mt * 16 + qrow + hrow * 8;
                if (m >= M) continue;
                float a0 = cc[hrow * 2 + 0];
                float a1 = cc[hrow * 2 + 1];
                float v0, v1;
                if (mode == 0) {
                    size_t off = (size_t)m * N + n0;
                    v0 = a0 + b0; v1 = a1 + b1;
                    *(float2*)&Cf[off] = make_float2(v0, v1);
                } else if (mode == 1) {
                    size_t off = (size_t)m * N + n0;
                    float2 r = *(const float2*)&res[off];
                    v0 = r.x + gelu_exact(a0 * (1.0f / Tt) + b0);
                    v1 = r.y + gelu_exact(a1 * (1.0f / Tt) + b1);
                    *(float2*)&Cf[off] = make_float2(v0, v1);
                } else if (mode == 3) {
                    size_t off = (size_t)m * N + n0;
                    float2 r = *(const float2*)&res[off];
                    v0 = r.x + gelu_exact(a0 + b0);
                    v1 = r.y + gelu_exact(a1 + b1);
                    *(float2*)&Cf[off] = make_float2(v0, v1);
                } else if (mode == 5) {
                    int seg = n0 >> 9, nn = n0 & 511;
                    __nv_bfloat16* dh = (seg == 0) ? g_qh : (seg == 1) ? g_kh : g_vh;
                    __nv_bfloat16* dl = (seg == 0) ? g_ql : (seg == 1) ? g_kl : g_vl;
                    float g0 = a0 + b0, g1 = a1 + b1;
                    __nv_bfloat16 h0 = __float2bfloat16(g0);
                    __nv_bfloat16 h1 = __float2bfloat16(g1);
                    __nv_bfloat162 hh = __nv_bfloat162(h0, h1);
                    __nv_bfloat162 ll = __floats2bfloat162_rn(g0 - __bfloat162float(h0),
                                                              g1 - __bfloat162float(h1));
                    size_t off = (size_t)m * Dd + nn;
                    *(__nv_bfloat162*)(dh + off) = hh;
                    *(__nv_bfloat162*)(dl + off) = ll;
                } else { // mode 2
                    size_t off = (size_t)m * N + n0;
                    float g0 = gelu_exact(a0 + b0);
                    float g1 = gelu_exact(a1 + b1);
                    __nv_bfloat16 h0 = __float2bfloat16(g0);
                    __nv_bfloat16 h1 = __float2bfloat16(g1);
                    __nv_bfloat162 hh = __nv_bfloat162(h0, h1);
                    __nv_bfloat162 ll = __floats2bfloat162_rn(g0 - __bfloat162float(h0),
                                                              g1 - __bfloat162float(h1));
                    *(__nv_bfloat162*)(Chi + off) = hh;
                    *(__nv_bfloat162*)(Clo + off) = ll;
                }
            }
        }
    }
}

// ================= tensor-core attention (bf16x3) — R10 version ==============
#define AKR 208
#define ALD 144
#define ASM_ONE (AKR*ALD)
#define ATT_SMEM (4*ASM_ONE)
#define TG 4

__global__ void __launch_bounds__(256, 1) attn_mma_k() {
    int bid = blockIdx.x;
    int h = bid & 7;
    int u = (bid >> 3) % Tt;
    int tg = (bid / (8 * Tt)) % (Tt / TG);
    int b = bid / (8 * Tt * (Tt / TG));

    extern __shared__ char smb_[];
    uint32_t skh = smem_u32(smb_);
    uint32_t skl = skh + ASM_ONE;
    uint32_t svh = skh + 2 * ASM_ONE;
    uint32_t svl = skh + 3 * ASM_ONE;

    int tid = threadIdx.x;
    int w = tid >> 5, lane = tid & 31;

    size_t kvbase = ((size_t)(b * Tt + u) * Pp) * Dd + h * DHd;

    for (int idx = tid; idx < AKR * 8; idx += 256) {
        int row = idx >> 3, seg = idx & 7;
        uint4 kh4 = make_uint4(0,0,0,0), kl4 = kh4, vh4 = kh4, vl4 = kh4;
        if (row < Pp) {
            size_t g = kvbase + (size_t)row * Dd + seg * 8;
            kh4 = *(const uint4*)&g_kh[g];
            kl4 = *(const uint4*)&g_kl[g];
            vh4 = *(const uint4*)&g_vh[g];
            vl4 = *(const uint4*)&g_vl[g];
        }
        uint32_t so = row * ALD + seg * 16;
        *(uint4*)(smb_ + so) = kh4;
        *(uint4*)(smb_ + ASM_ONE + so) = kl4;
        *(uint4*)(smb_ + 2*ASM_ONE + so) = vh4;
        *(uint4*)(smb_ + 3*ASM_ONE + so) = vl4;
    }
    __syncthreads();

    int gr = lane >> 2, qc = (lane & 3) * 2;
    int sel = lane >> 3, lr = lane & 7;
    uint32_t koff = ((sel >> 1) * 8 + lr) * ALD + (sel & 1) * 16;
    uint32_t voff = ((sel & 1) * 8 + lr) * ALD + (sel >> 1) * 16;

    for (int tau = w; tau < 13 * TG; tau += 8) {
        int tl = tau / 13, mt = tau % 13;
        int t = tg * TG + tl;
        size_t qbase = ((size_t)(b * Tt + t) * Pp) * Dd + h * DHd;
        float* Ob = g_av + ((size_t)((b * Tt + t) * Tt + u) * Pp) * Dd + h * DHd;

        int m0 = mt * 16;
        int r0 = min(m0 + gr, Pp - 1);
        int r1 = min(m0 + gr + 8, Pp - 1);

        uint32_t qa_h[4][4], qa_l[4][4];
        #pragma unroll
        for (int J = 0; J < 4; J++) {
            int c0 = J * 16 + qc;
            qa_h[J][0] = *(const uint32_t*)&g_qh[qbase + (size_t)r0 * Dd + c0];
            qa_h[J][1] = *(const uint32_t*)&g_qh[qbase + (size_t)r1 * Dd + c0];
            qa_h[J][2] = *(const uint32_t*)&g_qh[qbase + (size_t)r0 * Dd + c0 + 8];
            qa_h[J][3] = *(const uint32_t*)&g_qh[qbase + (size_t)r1 * Dd + c0 + 8];
            qa_l[J][0] = *(const uint32_t*)&g_ql[qbase + (size_t)r0 * Dd + c0];
            qa_l[J][1] = *(const uint32_t*)&g_ql[qbase + (size_t)r1 * Dd + c0];
            qa_l[J][2] = *(const uint32_t*)&g_ql[qbase + (size_t)r0 * Dd + c0 + 8];
            qa_l[J][3] = *(const uint32_t*)&g_ql[qbase + (size_t)r1 * Dd + c0 + 8];
        }

        float sc[26][4];
        #pragma unroll
        for (int nt = 0; nt < 26; nt++)
            #pragma unroll
            for (int i = 0; i < 4; i++) sc[nt][i] = 0.f;

        #pragma unroll
        for (int J = 0; J < 4; J++) {
            for (int ntp = 0; ntp < 12; ntp += 2) {
                uint32_t kb0 = ntp * (16 * ALD) + koff + J * 32;
                uint32_t kb1 = kb0 + 16 * ALD;
                uint32_t bh0[4], bl0[4], bh1[4], bl1[4];
                ldsm4(bh0, skh + kb0);
                ldsm4(bl0, skl + kb0);
                ldsm4(bh1, skh + kb1);
                ldsm4(bl1, skl + kb1);
                mma_bf16(sc[2*ntp],   qa_h[J], bh0[0], bh0[1]);
                mma_bf16(sc[2*ntp+1], qa_h[J], bh0[2], bh0[3]);
                mma_bf16(sc[2*ntp+2], qa_h[J], bh1[0], bh1[1]);
                mma_bf16(sc[2*ntp+3], qa_h[J], bh1[2], bh1[3]);
                mma_bf16(sc[2*ntp],   qa_h[J], bl0[0], bl0[1]);
                mma_bf16(sc[2*ntp+1], qa_h[J], bl0[2], bl0[3]);
                mma_bf16(sc[2*ntp+2], qa_h[J], bl1[0], bl1[1]);
                mma_bf16(sc[2*ntp+3], qa_h[J], bl1[2], bl1[3]);
                mma_bf16(sc[2*ntp],   qa_l[J], bh0[0], bh0[1]);
                mma_bf16(sc[2*ntp+1], qa_l[J], bh0[2], bh0[3]);
                mma_bf16(sc[2*ntp+2], qa_l[J], bh1[0], bh1[1]);
                mma_bf16(sc[2*ntp+3], qa_l[J], bh1[2], bh1[3]);
            }
            {
                uint32_t kb = 12 * (16 * ALD) + koff + J * 32;
                uint32_t bh[4], bl[4];
                ldsm4(bh, skh + kb);
                ldsm4(bl, skl + kb);
                mma_bf16(sc[24], qa_h[J], bh[0], bh[1]);
                mma_bf16(sc[25], qa_h[J], bh[2], bh[3]);
                mma_bf16(sc[24], qa_h[J], bl[0], bl[1]);
                mma_bf16(sc[25], qa_h[J], bl[2], bl[3]);
                mma_bf16(sc[24], qa_l[J], bh[0], bh[1]);
                mma_bf16(sc[25], qa_l[J], bh[2], bh[3]);
            }
        }

        float mx0 = -1e30f, mx1 = -1e30f;
        #pragma unroll
        for (int nt = 0; nt < 26; nt++) {
            int n0 = nt * 8 + qc;
            if (n0 >= Pp) {
                sc[nt][0] = sc[nt][1] = sc[nt][2] = sc[nt][3] = -1e30f;
            } else {
                sc[nt][0] *= 0.125f; sc[nt][1] *= 0.125f;
                sc[nt][2] *= 0.125f; sc[nt][3] *= 0.125f;
            }
            mx0 = fmaxf(mx0, fmaxf(sc[nt][0], sc[nt][1]));
            mx1 = fmaxf(mx1, fmaxf(sc[nt][2], sc[nt][3]));
        }
        mx0 = fmaxf(mx0, __shfl_xor_sync(0xffffffffu, mx0, 1));
        mx0 = fmaxf(mx0, __shfl_xor_sync(0xffffffffu, mx0, 2));
        mx1 = fmaxf(mx1, __shfl_xor_sync(0xffffffffu, mx1, 1));
        mx1 = fmaxf(mx1, __shfl_xor_sync(0xffffffffu, mx1, 2));
        float sum0 = 0.f, sum1 = 0.f;
        #pragma unroll
        for (int nt = 0; nt < 26; nt++) {
            sc[nt][0] = __expf(sc[nt][0] - mx0);
            sc[nt][1] = __expf(sc[nt][1] - mx0);
            sc[nt][2] = __expf(sc[nt][2] - mx1);
            sc[nt][3] = __expf(sc[nt][3] - mx1);
            sum0 += sc[nt][0] + sc[nt][1];
            sum1 += sc[nt][2] + sc[nt][3];
        }
        sum0 += __shfl_xor_sync(0xffffffffu, sum0, 1);
        sum0 += __shfl_xor_sync(0xffffffffu, sum0, 2);
        sum1 += __shfl_xor_sync(0xffffffffu, sum1, 1);
        sum1 += __shfl_xor_sync(0xffffffffu, sum1, 2);
        float rv0 = 1.0f / sum0, rv1 = 1.0f / sum1;
        #pragma unroll
        for (int nt = 0; nt < 26; nt++) {
            sc[nt][0] *= rv0; sc[nt][1] *= rv0;
            sc[nt][2] *= rv1; sc[nt][3] *= rv1;
        }

        float oacc[8][4];
        #pragma unroll
        for (int i = 0; i < 8; i++)
            #pragma unroll
            for (int jx = 0; jx < 4; jx++) oacc[i][jx] = 0.f;

        for (int J = 0; J < 13; J++) {
            uint32_t pa_h[4], pa_l[4];
            {
                float p00 = sc[2*J][0],   p01 = sc[2*J][1];
                float p10 = sc[2*J][2],   p11 = sc[2*J][3];
                float p20 = sc[2*J+1][0], p21 = sc[2*J+1][1];
                float p30 = sc[2*J+1][2], p31 = sc[2*J+1][3];
                __nv_bfloat16 hh;
                float l00, l01, l10, l11, l20, l21, l30, l31;
                hh = __float2bfloat16(p00); l00 = p00 - __bfloat162float(hh);
                hh = __float2bfloat16(p01); l01 = p01 - __bfloat162float(hh);
                hh = __float2bfloat16(p10); l10 = p10 - __bfloat162float(hh);
                hh = __float2bfloat16(p11); l11 = p11 - __bfloat162float(hh);
                hh = __float2bfloat16(p20); l20 = p20 - __bfloat162float(hh);
                hh = __float2bfloat16(p21); l21 = p21 - __bfloat162float(hh);
                hh = __float2bfloat16(p30); l30 = p30 - __bfloat162float(hh);
                hh = __float2bfloat16(p31); l31 = p31 - __bfloat162float(hh);
                pa_h[0] = pack_bf16(p00, p01);
                pa_h[1] = pack_bf16(p10, p11);
                pa_h[2] = pack_bf16(p20, p21);
                pa_h[3] = pack_bf16(p30, p31);
                pa_l[0] = pack_bf16(l00, l01);
                pa_l[1] = pack_bf16(l10, l11);
                pa_l[2] = pack_bf16(l20, l21);
                pa_l[3] = pack_bf16(l30, l31);
            }
            uint32_t vb = J * (16 * ALD) + voff;
            uint32_t bh[4][4], bl[4][4];
            #pragma unroll
            for (int np = 0; np < 4; np++) {
                ldsm4t(bh[np], svh + vb + np * 32);
                ldsm4t(bl[np], svl + vb + np * 32);
            }
            #pragma unroll
            for (int np = 0; np < 4; np++) {
                mma_bf16(oacc[2*np],   pa_h, bh[np][0], bh[np][1]);
                mma_bf16(oacc[2*np+1], pa_h, bh[np][2], bh[np][3]);
            }
            #pragma unroll
            for (int np = 0; np < 4; np++) {
                mma_bf16(oacc[2*np],   pa_h, bl[np][0], bl[np][1]);
                mma_bf16(oacc[2*np+1], pa_h, bl[np][2], bl[np][3]);
            }
            #pragma unroll
            for (int np = 0; np < 4; np++) {
                mma_bf16(oacc[2*np],   pa_l, bh[np][0], bh[np][1]);
                mma_bf16(oacc[2*np+1], pa_l, bh[np][2], bh[np][3]);
            }
        }

        int p0r = m0 + gr, p1r = m0 + gr + 8;
        #pragma unroll
        for (int nt2 = 0; nt2 < 8; nt2++) {
            int n = nt2 * 8 + qc;
            if (p0r < Pp)
                *(float2*)&Ob[(size_t)p0r * Dd + n] = make_float2(oacc[nt2][0], oacc[nt2][1]);
            if (p1r < Pp)
                *(float2*)&Ob[(size_t)p1r * Dd + n] = make_float2(oacc[nt2][2], oacc[nt2][3]);
        }
    }
}

// ---------------- launch ----------------
extern "C" void kernel_launch(void* const* d_in, const int* in_sizes, int n_in,
                              void* d_out, int out_size) {
    const float* x    = (const float*)d_in[0];
    const float* Wq   = (const float*)d_in[1];
    const float* bq   = (const float*)d_in[2];
    const float* Wk   = (const float*)d_in[3];
    const float* bk   = (const float*)d_in[4];
    const float* Wv   = (const float*)d_in[5];
    const float* bv   = (const float*)d_in[6];
    const float* in_a = (const float*)d_in[7];
    const float* in_b = (const float*)d_in[8];
    const float* at_a = (const float*)d_in[9];
    const float* at_b = (const float*)d_in[10];
    const float* ou_a = (const float*)d_in[11];
    const float* ou_b = (const float*)d_in[12];
    const float* Wt   = (const float*)d_in[13];
    const float* bt   = (const float*)d_in[14];
    const float* pos  = (const float*)d_in[15];
    const float* W1   = (const float*)d_in[16];
    const float* b1   = (const float*)d_in[17];
    const float* W2   = (const float*)d_in[18];
    const float* b2   = (const float*)d_in[19];

    float *pav, *pxres, *pbtsum, *pbqkv;
    __nv_bfloat16 *px2h, *px2l, *pyh, *pyl, *phh, *phl, *pwh, *pwl;
    cudaGetSymbolAddress((void**)&pav,  g_av);
    cudaGetSymbolAddress((void**)&pxres,g_xres);
    cudaGetSymbolAddress((void**)&pbtsum, g_btsum);
    cudaGetSymbolAddress((void**)&pbqkv, g_bqkv);
    cudaGetSymbolAddress((void**)&px2h, g_x2h);
    cudaGetSymbolAddress((void**)&px2l, g_x2l);
    cudaGetSymbolAddress((void**)&pyh,  g_yh);
    cudaGetSymbolAddress((void**)&pyl,  g_yl);
    cudaGetSymbolAddress((void**)&phh,  g_hh);
    cudaGetSymbolAddress((void**)&phl,  g_hl);
    cudaGetSymbolAddress((void**)&pwh,  w_hi);
    cudaGetSymbolAddress((void**)&pwl,  w_lo);

    cudaFuncSetAttribute(attn_mma_k, cudaFuncAttributeMaxDynamicSharedMemorySize,
                         ATT_SMEM);
    cudaFuncSetAttribute(gemm_mma_k, cudaFuncAttributeMaxDynamicSharedMemorySize,
                         GM_SMEM);

    // (0) pre1: LN(x) + QKV weight/bias convert
    pre1_k<<<4248, 256>>>(x, in_a, in_b, Wq, Wk, Wv, bq, bk, bv);
    // (1) merged QKV projection (mode 5), N = 1536
    dim3 gq(1536 / 128, (M1 + 127) / 128);
    gemm_mma_k<<<gq, 256, GM_SMEM>>>(px2h, px2l, pwh + OQ, pwl + OQ, pbqkv, nullptr,
                                     nullptr, nullptr, nullptr, M1, 1536, Dd, 5);
    // (2) pre2: Wt/W1/W2 convert + btsum (no deps on attention)
    pre2_k<<<16386, 256>>>(Wt, W1, W2, bt);
    // (3) tensor-core attention -> g_av  (ncu capture slot)
    attn_mma_k<<<Bq * (Tt / TG) * Tt * Hh, 256, ATT_SMEM>>>();
    // (4) LN(av)+pos -> y hi/lo
    ln_bf_k<<<ROWS_AV / 8, 256>>>(pav, at_a, at_b, pos, pyh, pyl, POSMOD);
    // (5) tc contraction (mode 1, L2-swizzled 1D grid)
    gemm_mma_k<<<296, 256, GM_SMEM>>>(pyh, pyl, pwh + OT, pwl + OT, pbtsum, x,
                                      pxres, nullptr, nullptr, M1, Dd, Tt * Dd, 1);
    // (6) LN(xres) -> x2 hi/lo
    ln_bf_k<<<M1 / 8, 256>>>(pxres, ou_a, ou_b, nullptr, px2h, px2l, 1);
    // (7) MLP1 (mode 2)
    dim3 g1(2 * Dd / 128, (M1 + 127) / 128);
    gemm_mma_k<<<g1, 256, GM_SMEM>>>(px2h, px2l, pwh + O1, pwl + O1, b1, nullptr,
                                     nullptr, phh, phl, M1, 2 * Dd, Dd, 2);
    // (8) MLP2 (mode 3) -> d_out
    dim3 gtc(Dd / 128, (M1 + 127) / 128);
    gemm_mma_k<<<gtc, 256, GM_SMEM>>>(phh, phl, pwh + O2, pwl + O2, b2, pxres,
                                      (float*)d_out, nullptr, nullptr, M1, Dd, 2 * Dd, 3);
}

// round 14
// speedup vs baseline: 1.0843x; 1.0843x over previous
#include <cuda_runtime.h>
#include <cuda_bf16.h>
#include <math.h>
#include <stdint.h>

#define Bq 4
#define Tt 12
#define Pp 196
#define Dd 512
#define Hh 8
#define DHd 64
#define EPSV 1e-6f

#define M1 (Bq*Tt*Pp)            // 9408
#define ROWS_AV (Bq*Tt*Tt*Pp)    // 112896
#define POSMOD (Tt*Tt*Pp)        // 28224

#define OQ 0
#define OKo 262144
#define OV  524288
#define OT  786432
#define O1  3932160
#define O2  4456448
#define WTOT 4980736

// ---------------- scratch ----------------
__device__ float g_av[(size_t)ROWS_AV*Dd];
__device__ float g_xres[M1*Dd];
__device__ float g_btsum[Dd];
__device__ float g_bqkv[3*Dd];
__device__ __nv_bfloat16 g_x2h[M1*Dd],  g_x2l[M1*Dd];
__device__ __nv_bfloat16 g_qh[M1*Dd], g_ql[M1*Dd];
__device__ __nv_bfloat16 g_kh[M1*Dd], g_kl[M1*Dd];
__device__ __nv_bfloat16 g_vh[M1*Dd], g_vl[M1*Dd];
__device__ __nv_bfloat16 g_yh[(size_t)ROWS_AV*Dd], g_yl[(size_t)ROWS_AV*Dd];
__device__ __nv_bfloat16 g_hh[M1*2*Dd], g_hl[M1*2*Dd];
__device__ __nv_bfloat16 w_hi[WTOT], w_lo[WTOT];

// ---------------- helpers ----------------
__device__ __forceinline__ float gelu_exact(float x) {
    return 0.5f * x * (1.0f + erff(x * 0.70710678118654752f));
}
__device__ __forceinline__ uint32_t smem_u32(const void* p) {
    uint32_t a;
    asm("{ .reg .u64 t; cvta.to.shared.u64 t, %1; cvt.u32.u64 %0, t; }" : "=r"(a) : "l"(p));
    return a;
}
__device__ __forceinline__ void ldsm4(uint32_t* r, uint32_t a) {
    asm volatile("ldmatrix.sync.aligned.m8n8.x4.shared.b16 {%0,%1,%2,%3}, [%4];"
                 : "=r"(r[0]), "=r"(r[1]), "=r"(r[2]), "=r"(r[3]) : "r"(a));
}
__device__ __forceinline__ void ldsm4t(uint32_t* r, uint32_t a) {
    asm volatile("ldmatrix.sync.aligned.m8n8.x4.trans.shared.b16 {%0,%1,%2,%3}, [%4];"
                 : "=r"(r[0]), "=r"(r[1]), "=r"(r[2]), "=r"(r[3]) : "r"(a));
}
__device__ __forceinline__ void mma_bf16(float* c, const uint32_t* a, uint32_t b0, uint32_t b1) {
    asm volatile(
        "mma.sync.aligned.m16n8k16.row.col.f32.bf16.bf16.f32 "
        "{%0,%1,%2,%3}, {%4,%5,%6,%7}, {%8,%9}, {%0,%1,%2,%3};"
        : "+f"(c[0]), "+f"(c[1]), "+f"(c[2]), "+f"(c[3])
        : "r"(a[0]), "r"(a[1]), "r"(a[2]), "r"(a[3]), "r"(b0), "r"(b1));
}
__device__ __forceinline__ void cpa16(uint32_t s, const void* g) {
    asm volatile("cp.async.cg.shared.global [%0], [%1], 16;" :: "r"(s), "l"(g));
}
#define CPA_COMMIT() asm volatile("cp.async.commit_group;" ::: "memory")
#define CPA_WAIT(n)  asm volatile("cp.async.wait_group %0;" :: "n"(n) : "memory")

__device__ __forceinline__ uint32_t pack_bf16(float a, float b) {
    __nv_bfloat162 t = __floats2bfloat162_rn(a, b);
    return *(uint32_t*)&t;
}
__device__ __forceinline__ void split_store(__nv_bfloat16* hi, __nv_bfloat16* lo,
                                            size_t i, float v) {
    __nv_bfloat16 h = __float2bfloat16(v);
    hi[i] = h;
    lo[i] = __float2bfloat16(v - __bfloat162float(h));
}

// ---------------- LN row body (warp-per-row) ----------------
__device__ __forceinline__ void ln_row(const float* __restrict__ in,
                                       const float* __restrict__ al,
                                       const float* __restrict__ be,
                                       const float* __restrict__ pos,
                                       __nv_bfloat16* __restrict__ oh,
                                       __nv_bfloat16* __restrict__ ol,
                                       int posmod, int row, int lane) {
    const float* rp = in + (size_t)row * Dd;
    float4 v[4];
    float s = 0.f, sq = 0.f;
    #pragma unroll
    for (int j = 0; j < 4; j++) {
        v[j] = *(const float4*)&rp[lane * 4 + j * 128];
        s  += v[j].x + v[j].y + v[j].z + v[j].w;
        sq += v[j].x*v[j].x + v[j].y*v[j].y + v[j].z*v[j].z + v[j].w*v[j].w;
    }
    #pragma unroll
    for (int o = 16; o; o >>= 1) {
        s  += __shfl_xor_sync(0xffffffffu, s,  o);
        sq += __shfl_xor_sync(0xffffffffu, sq, o);
    }
    float mu  = s * (1.0f / Dd);
    float var = (sq - (float)Dd * mu * mu) * (1.0f / (Dd - 1));
    float inv = 1.0f / (sqrtf(fmaxf(var, 0.f)) + EPSV);
    const float* pp = pos ? (pos + (size_t)(row % posmod) * Dd) : nullptr;

    #pragma unroll
    for (int j = 0; j < 4; j++) {
        int c = lane * 4 + j * 128;
        float4 a = *(const float4*)&al[c];
        float4 b = *(const float4*)&be[c];
        float o0 = a.x * (v[j].x - mu) * inv + b.x;
        float o1 = a.y * (v[j].y - mu) * inv + b.y;
        float o2 = a.z * (v[j].z - mu) * inv + b.z;
        float o3 = a.w * (v[j].w - mu) * inv + b.w;
        if (pp) {
            float4 p = *(const float4*)&pp[c];
            o0 += p.x; o1 += p.y; o2 += p.z; o3 += p.w;
        }
        __nv_bfloat16 h0 = __float2bfloat16(o0);
        __nv_bfloat16 h1 = __float2bfloat16(o1);
        __nv_bfloat16 h2 = __float2bfloat16(o2);
        __nv_bfloat16 h3 = __float2bfloat16(o3);
        uint2 hv, lv;
        __nv_bfloat162 hh01 = __nv_bfloat162(h0, h1);
        __nv_bfloat162 hh23 = __nv_bfloat162(h2, h3);
        hv.x = *(uint32_t*)&hh01;
        hv.y = *(uint32_t*)&hh23;
        __nv_bfloat162 ll01 = __floats2bfloat162_rn(o0 - __bfloat162float(h0),
                                                    o1 - __bfloat162float(h1));
        __nv_bfloat162 ll23 = __floats2bfloat162_rn(o2 - __bfloat162float(h2),
                                                    o3 - __bfloat162float(h3));
        lv.x = *(uint32_t*)&ll01;
        lv.y = *(uint32_t*)&ll23;
        *(uint2*)&oh[(size_t)row * Dd + c] = hv;
        *(uint2*)&ol[(size_t)row * Dd + c] = lv;
    }
}

// ---------------- LayerNorm standalone ----------------
__global__ void ln_bf_k(const float* __restrict__ in,
                        const float* __restrict__ al,
                        const float* __restrict__ be,
                        const float* __restrict__ pos,
                        __nv_bfloat16* __restrict__ oh,
                        __nv_bfloat16* __restrict__ ol,
                        int posmod) {
    int w = threadIdx.x >> 5, lane = threadIdx.x & 31;
    ln_row(in, al, be, pos, oh, ol, posmod, blockIdx.x * 8 + w, lane);
}

// ---------------- pre1: LN(x) + QKV weight/bias convert ----------------
__global__ void pre1_k(const float* __restrict__ x,
                       const float* __restrict__ in_a, const float* __restrict__ in_b,
                       const float* __restrict__ Wq, const float* __restrict__ Wk,
                       const float* __restrict__ Wv,
                       const float* __restrict__ bq, const float* __restrict__ bk,
                       const float* __restrict__ bv) {
    int bid = blockIdx.x, tid = threadIdx.x;
    if (bid < 1176) {
        int w = tid >> 5, lane = tid & 31;
        ln_row(x, in_a, in_b, nullptr, g_x2h, g_x2l, 1, bid * 8 + w, lane);
    } else {
        int i = (bid - 1176) * 256 + tid;
        if (i < 3 * Dd)
            g_bqkv[i] = (i < Dd) ? bq[i] : (i < 2 * Dd) ? bk[i - Dd] : bv[i - 2 * Dd];
        if (i < 786432) {
            int seg = i >> 18, off = i & 262143;
            float v = (seg == 0) ? Wq[off] : (seg == 1) ? Wk[off] : Wv[off];
            split_store(w_hi, w_lo, i, v);
        }
    }
}

// ---------------- pre2: Wt/W1/W2 convert + btsum ----------
__global__ void pre2_k(const float* __restrict__ Wt, const float* __restrict__ W1,
                       const float* __restrict__ W2, const float* __restrict__ bt) {
    int bid = blockIdx.x, tid = threadIdx.x;
    if (bid < 16384) {
        int i = bid * 256 + tid;
        float v; int di;
        if (i < 3145728)      { v = Wt[i];            di = OT + i; }
        else if (i < 3670016) { v = W1[i - 3145728];  di = O1 + (i - 3145728); }
        else                  { v = W2[i - 3670016];  di = O2 + (i - 3670016); }
        split_store(w_hi, w_lo, di, v);
    } else {
        int e = (bid - 16384) * 256 + tid;
        if (e < Dd) {
            float s = 0.f;
            #pragma unroll
            for (int u = 0; u < Tt; u++) s += bt[u * Dd + e];
            g_btsum[e] = s;
        }
    }
}

// ================= mma.sync bf16x3 GEMM v2: 2 blocks/SM (unchanged) ==========
#define LDP 80
#define TILE_B (128*LDP)
#define STAGE_B (4*TILE_B)
#define GM_SMEM (2*STAGE_B)

__global__ void __launch_bounds__(256, 2) gemm_mma_k(
    const __nv_bfloat16* __restrict__ Ahi, const __nv_bfloat16* __restrict__ Alo,
    const __nv_bfloat16* __restrict__ Bhi, const __nv_bfloat16* __restrict__ Blo,
    const float* __restrict__ bias, const float* __restrict__ res,
    float* __restrict__ Cf, __nv_bfloat16* __restrict__ Chi, __nv_bfloat16* __restrict__ Clo,
    int M, int N, int K, int mode)
{
    extern __shared__ char smc[];
    int tid = threadIdx.x;
    int wid = tid >> 5, lane = tid & 31;
    int bm, bn;
    if (mode == 1) {
        int bid2 = blockIdx.x;
        int g = bid2 >> 5, r = bid2 & 31;
        int bmi, bni;
        if (g < 9) { bmi = g * 8 + (r & 7); bni = r >> 3; }
        else       { bmi = 72 + (r & 1);    bni = r >> 1; }
        bm = bmi * 128; bn = bni * 128;
    } else {
        bm = blockIdx.y * 128; bn = blockIdx.x * 128;
    }
    int wm = (wid >> 2) * 64;
    int wn = (wid & 3) * 32;

    int lrow = tid >> 1;
    int lhalf = tid & 1;
    int am = min(bm + lrow, M - 1);
    size_t abase;
    if (mode == 1) {
        int b_ = am / (Tt * Pp), r_ = am % (Tt * Pp);
        int t_ = r_ / Pp, p_ = r_ % Pp;
        abase = ((size_t)(b_ * (Tt * Tt) + t_ * Tt) * Pp + p_) * Dd;
    } else {
        abase = (size_t)am * K;
    }
    int brow = bn + lrow;
    uint32_t smrow = lrow * LDP;

    int NC = K / 32;

    auto load_stage = [&](int buf, int c) {
        size_t aoff, boff;
        if (mode == 1) {
            int u = c >> 4, d0 = (c & 15) * 32;
            aoff = abase + (size_t)u * (Pp * Dd) + d0;
            boff = (size_t)u * (Dd * Dd) + (size_t)brow * Dd + d0;
        } else {
            aoff = abase + c * 32;
            boff = (size_t)brow * K + c * 32;
        }
        uint32_t sb = smem_u32(smc) + buf * STAGE_B + smrow;
        #pragma unroll
        for (int i = 0; i < 2; i++) {
            int colk = lhalf * 16 + i * 8;
            uint32_t so = sb + colk * 2;
            cpa16(so,              Ahi + aoff + colk);
            cpa16(so + TILE_B,     Alo + aoff + colk);
            cpa16(so + 2*TILE_B,   Bhi + boff + colk);
            cpa16(so + 3*TILE_B,   Blo + boff + colk);
        }
    };

    int sel = lane >> 3, lr = lane & 7;
    int a_m = wm + (sel & 1) * 8 + lr;
    int b_n = wn + (sel >> 1) * 8 + lr;
    uint32_t smb = smem_u32(smc);
    uint32_t aoffB = a_m * LDP + (sel >> 1) * 16;
    uint32_t boffB = b_n * LDP + (sel & 1) * 16;

    float acc[4][4][4] = {};

    load_stage(0, 0);
    CPA_COMMIT();

    for (int c = 0; c < NC; c++) {
        int buf = c & 1;
        if (c + 1 < NC) {
            load_stage(buf ^ 1, c + 1);
            CPA_COMMIT();
            CPA_WAIT(1);
        } else {
            CPA_WAIT(0);
        }
        __syncthreads();

        uint32_t base = smb + buf * STAGE_B;
        uint32_t aHb = base + aoffB;
        uint32_t aLb = aHb + TILE_B;
        uint32_t bHb = base + 2*TILE_B + boffB;
        uint32_t bLb = bHb + TILE_B;

        #pragma unroll
        for (int kk = 0; kk < 2; kk++) {
            uint32_t ko = kk * 32;
            uint32_t bH[2][4], bL[2][4];
            #pragma unroll
            for (int nt2 = 0; nt2 < 2; nt2++) {
                ldsm4(bH[nt2], bHb + nt2 * (16 * LDP) + ko);
                ldsm4(bL[nt2], bLb + nt2 * (16 * LDP) + ko);
            }
            #pragma unroll
            for (int mt = 0; mt < 4; mt++) {
                uint32_t aH[4], aL[4];
                ldsm4(aH, aHb + mt * (16 * LDP) + ko);
                ldsm4(aL, aLb + mt * (16 * LDP) + ko);
                #pragma unroll
                for (int nt = 0; nt < 4; nt++) {
                    int s2 = nt >> 1, pp = (nt & 1) * 2;
                    mma_bf16(acc[mt][nt], aH, bH[s2][pp], bH[s2][pp+1]);
                }
                #pragma unroll
                for (int nt = 0; nt < 4; nt++) {
                    int s2 = nt >> 1, pp = (nt & 1) * 2;
                    mma_bf16(acc[mt][nt], aH, bL[s2][pp], bL[s2][pp+1]);
                }
                #pragma unroll
                for (int nt = 0; nt < 4; nt++) {
                    int s2 = nt >> 1, pp = (nt & 1) * 2;
                    mma_bf16(acc[mt][nt], aL, bH[s2][pp], bH[s2][pp+1]);
                }
            }
        }
        __syncthreads();
    }

    int qrow = lane >> 2;
    int qcol = (lane & 3) * 2;
    #pragma unroll
    for (int mt = 0; mt < 4; mt++) {
        #pragma unroll
        for (int nt = 0; nt < 4; nt++) {
            float* cc = acc[mt][nt];
            int n0 = bn + wn + nt * 8 + qcol;
            float b0 = bias[n0], b1 = bias[n0 + 1];
            #pragma unroll
            for (int hrow = 0; hrow < 2; hrow++) {
                int m = bm + wm + mt * 16 + qrow + hrow * 8;
                if (m >= M) continue;
                float a0 = cc[hrow * 2 + 0];
                float a1 = cc[hrow * 2 + 1];
                float v0, v1;
                if (mode == 0) {
                    size_t off = (size_t)m * N + n0;
                    v0 = a0 + b0; v1 = a1 + b1;
                    *(float2*)&Cf[off] = make_float2(v0, v1);
                } else if (mode == 1) {
                    size_t off = (size_t)m * N + n0;
                    float2 r = *(const float2*)&res[off];
                    v0 = r.x + gelu_exact(a0 * (1.0f / Tt) + b0);
                    v1 = r.y + gelu_exact(a1 * (1.0f / Tt) + b1);
                    *(float2*)&Cf[off] = make_float2(v0, v1);
                } else if (mode == 3) {
                    size_t off = (size_t)m * N + n0;
                    float2 r = *(const float2*)&res[off];
                    v0 = r.x + gelu_exact(a0 + b0);
                    v1 = r.y + gelu_exact(a1 + b1);
                    *(float2*)&Cf[off] = make_float2(v0, v1);
                } else if (mode == 5) {
                    int seg = n0 >> 9, nn = n0 & 511;
                    __nv_bfloat16* dh = (seg == 0) ? g_qh : (seg == 1) ? g_kh : g_vh;
                    __nv_bfloat16* dl = (seg == 0) ? g_ql : (seg == 1) ? g_kl : g_vl;
                    float g0 = a0 + b0, g1 = a1 + b1;
                    __nv_bfloat16 h0 = __float2bfloat16(g0);
                    __nv_bfloat16 h1 = __float2bfloat16(g1);
                    __nv_bfloat162 hh = __nv_bfloat162(h0, h1);
                    __nv_bfloat162 ll = __floats2bfloat162_rn(g0 - __bfloat162float(h0),
                                                              g1 - __bfloat162float(h1));
                    size_t off = (size_t)m * Dd + nn;
                    *(__nv_bfloat162*)(dh + off) = hh;
                    *(__nv_bfloat162*)(dl + off) = ll;
                } else { // mode 2
                    size_t off = (size_t)m * N + n0;
                    float g0 = gelu_exact(a0 + b0);
                    float g1 = gelu_exact(a1 + b1);
                    __nv_bfloat16 h0 = __float2bfloat16(g0);
                    __nv_bfloat16 h1 = __float2bfloat16(g1);
                    __nv_bfloat162 hh = __nv_bfloat162(h0, h1);
                    __nv_bfloat162 ll = __floats2bfloat162_rn(g0 - __bfloat162float(h0),
                                                              g1 - __bfloat162float(h1));
                    *(__nv_bfloat162*)(Chi + off) = hh;
                    *(__nv_bfloat162*)(Clo + off) = ll;
                }
            }
        }
    }
}

// ================= tensor-core attention — precision-trimmed bf16x2 ==========
// QK: q_hi*(k_hi + k_lo)   (q_lo term dropped; score error ~4e-4)
// PV: p_hi*(v_hi + v_lo)   (p_lo term dropped; av rel error ~2e-3)
#define AKR 208
#define ALD 144
#define ASM_ONE (AKR*ALD)
#define ATT_SMEM (4*ASM_ONE)
#define TG 4

__global__ void __launch_bounds__(256, 1) attn_mma_k() {
    int bid = blockIdx.x;
    int h = bid & 7;
    int u = (bid >> 3) % Tt;
    int tg = (bid / (8 * Tt)) % (Tt / TG);
    int b = bid / (8 * Tt * (Tt / TG));

    extern __shared__ char smb_[];
    uint32_t skh = smem_u32(smb_);
    uint32_t skl = skh + ASM_ONE;
    uint32_t svh = skh + 2 * ASM_ONE;
    uint32_t svl = skh + 3 * ASM_ONE;

    int tid = threadIdx.x;
    int w = tid >> 5, lane = tid & 31;

    size_t kvbase = ((size_t)(b * Tt + u) * Pp) * Dd + h * DHd;

    for (int idx = tid; idx < AKR * 8; idx += 256) {
        int row = idx >> 3, seg = idx & 7;
        uint4 kh4 = make_uint4(0,0,0,0), kl4 = kh4, vh4 = kh4, vl4 = kh4;
        if (row < Pp) {
            size_t g = kvbase + (size_t)row * Dd + seg * 8;
            kh4 = *(const uint4*)&g_kh[g];
            kl4 = *(const uint4*)&g_kl[g];
            vh4 = *(const uint4*)&g_vh[g];
            vl4 = *(const uint4*)&g_vl[g];
        }
        uint32_t so = row * ALD + seg * 16;
        *(uint4*)(smb_ + so) = kh4;
        *(uint4*)(smb_ + ASM_ONE + so) = kl4;
        *(uint4*)(smb_ + 2*ASM_ONE + so) = vh4;
        *(uint4*)(smb_ + 3*ASM_ONE + so) = vl4;
    }
    __syncthreads();

    int gr = lane >> 2, qc = (lane & 3) * 2;
    int sel = lane >> 3, lr = lane & 7;
    uint32_t koff = ((sel >> 1) * 8 + lr) * ALD + (sel & 1) * 16;
    uint32_t voff = ((sel & 1) * 8 + lr) * ALD + (sel >> 1) * 16;

    for (int tau = w; tau < 13 * TG; tau += 8) {
        int tl = tau / 13, mt = tau % 13;
        int t = tg * TG + tl;
        size_t qbase = ((size_t)(b * Tt + t) * Pp) * Dd + h * DHd;
        float* Ob = g_av + ((size_t)((b * Tt + t) * Tt + u) * Pp) * Dd + h * DHd;

        int m0 = mt * 16;
        int r0 = min(m0 + gr, Pp - 1);
        int r1 = min(m0 + gr + 8, Pp - 1);

        uint32_t qa_h[4][4];
        #pragma unroll
        for (int J = 0; J < 4; J++) {
            int c0 = J * 16 + qc;
            qa_h[J][0] = *(const uint32_t*)&g_qh[qbase + (size_t)r0 * Dd + c0];
            qa_h[J][1] = *(const uint32_t*)&g_qh[qbase + (size_t)r1 * Dd + c0];
            qa_h[J][2] = *(const uint32_t*)&g_qh[qbase + (size_t)r0 * Dd + c0 + 8];
            qa_h[J][3] = *(const uint32_t*)&g_qh[qbase + (size_t)r1 * Dd + c0 + 8];
        }

        float sc[26][4];
        #pragma unroll
        for (int nt = 0; nt < 26; nt++)
            #pragma unroll
            for (int i = 0; i < 4; i++) sc[nt][i] = 0.f;

        #pragma unroll
        for (int J = 0; J < 4; J++) {
            for (int ntp = 0; ntp < 12; ntp += 2) {
                uint32_t kb0 = ntp * (16 * ALD) + koff + J * 32;
                uint32_t kb1 = kb0 + 16 * ALD;
                uint32_t bh0[4], bl0[4], bh1[4], bl1[4];
                ldsm4(bh0, skh + kb0);
                ldsm4(bl0, skl + kb0);
                ldsm4(bh1, skh + kb1);
                ldsm4(bl1, skl + kb1);
                mma_bf16(sc[2*ntp],   qa_h[J], bh0[0], bh0[1]);
                mma_bf16(sc[2*ntp+1], qa_h[J], bh0[2], bh0[3]);
                mma_bf16(sc[2*ntp+2], qa_h[J], bh1[0], bh1[1]);
                mma_bf16(sc[2*ntp+3], qa_h[J], bh1[2], bh1[3]);
                mma_bf16(sc[2*ntp],   qa_h[J], bl0[0], bl0[1]);
                mma_bf16(sc[2*ntp+1], qa_h[J], bl0[2], bl0[3]);
                mma_bf16(sc[2*ntp+2], qa_h[J], bl1[0], bl1[1]);
                mma_bf16(sc[2*ntp+3], qa_h[J], bl1[2], bl1[3]);
            }
            {
                uint32_t kb = 12 * (16 * ALD) + koff + J * 32;
                uint32_t bh[4], bl[4];
                ldsm4(bh, skh + kb);
                ldsm4(bl, skl + kb);
                mma_bf16(sc[24], qa_h[J], bh[0], bh[1]);
                mma_bf16(sc[25], qa_h[J], bh[2], bh[3]);
                mma_bf16(sc[24], qa_h[J], bl[0], bl[1]);
                mma_bf16(sc[25], qa_h[J], bl[2], bl[3]);
            }
        }

        float mx0 = -1e30f, mx1 = -1e30f;
        #pragma unroll
        for (int nt = 0; nt < 26; nt++) {
            int n0 = nt * 8 + qc;
            if (n0 >= Pp) {
                sc[nt][0] = sc[nt][1] = sc[nt][2] = sc[nt][3] = -1e30f;
            } else {
                sc[nt][0] *= 0.125f; sc[nt][1] *= 0.125f;
                sc[nt][2] *= 0.125f; sc[nt][3] *= 0.125f;
            }
            mx0 = fmaxf(mx0, fmaxf(sc[nt][0], sc[nt][1]));
            mx1 = fmaxf(mx1, fmaxf(sc[nt][2], sc[nt][3]));
        }
        mx0 = fmaxf(mx0, __shfl_xor_sync(0xffffffffu, mx0, 1));
        mx0 = fmaxf(mx0, __shfl_xor_sync(0xffffffffu, mx0, 2));
        mx1 = fmaxf(mx1, __shfl_xor_sync(0xffffffffu, mx1, 1));
        mx1 = fmaxf(mx1, __shfl_xor_sync(0xffffffffu, mx1, 2));
        float sum0 = 0.f, sum1 = 0.f;
        #pragma unroll
        for (int nt = 0; nt < 26; nt++) {
            sc[nt][0] = __expf(sc[nt][0] - mx0);
            sc[nt][1] = __expf(sc[nt][1] - mx0);
            sc[nt][2] = __expf(sc[nt][2] - mx1);
            sc[nt][3] = __expf(sc[nt][3] - mx1);
            sum0 += sc[nt][0] + sc[nt][1];
            sum1 += sc[nt][2] + sc[nt][3];
        }
        sum0 += __shfl_xor_sync(0xffffffffu, sum0, 1);
        sum0 += __shfl_xor_sync(0xffffffffu, sum0, 2);
        sum1 += __shfl_xor_sync(0xffffffffu, sum1, 1);
        sum1 += __shfl_xor_sync(0xffffffffu, sum1, 2);
        float rv0 = 1.0f / sum0, rv1 = 1.0f / sum1;
        #pragma unroll
        for (int nt = 0; nt < 26; nt++) {
            sc[nt][0] *= rv0; sc[nt][1] *= rv0;
            sc[nt][2] *= rv1; sc[nt][3] *= rv1;
        }

        float oacc[8][4];
        #pragma unroll
        for (int i = 0; i < 8; i++)
            #pragma unroll
            for (int jx = 0; jx < 4; jx++) oacc[i][jx] = 0.f;

        for (int J = 0; J < 13; J++) {
            uint32_t pa_h[4];
            pa_h[0] = pack_bf16(sc[2*J][0],   sc[2*J][1]);
            pa_h[1] = pack_bf16(sc[2*J][2],   sc[2*J][3]);
            pa_h[2] = pack_bf16(sc[2*J+1][0], sc[2*J+1][1]);
            pa_h[3] = pack_bf16(sc[2*J+1][2], sc[2*J+1][3]);

            uint32_t vb = J * (16 * ALD) + voff;
            uint32_t bh[4][4], bl[4][4];
            #pragma unroll
            for (int np = 0; np < 4; np++) {
                ldsm4t(bh[np], svh + vb + np * 32);
                ldsm4t(bl[np], svl + vb + np * 32);
            }
            #pragma unroll
            for (int np = 0; np < 4; np++) {
                mma_bf16(oacc[2*np],   pa_h, bh[np][0], bh[np][1]);
                mma_bf16(oacc[2*np+1], pa_h, bh[np][2], bh[np][3]);
            }
            #pragma unroll
            for (int np = 0; np < 4; np++) {
                mma_bf16(oacc[2*np],   pa_h, bl[np][0], bl[np][1]);
                mma_bf16(oacc[2*np+1], pa_h, bl[np][2], bl[np][3]);
            }
        }

        int p0r = m0 + gr, p1r = m0 + gr + 8;
        #pragma unroll
        for (int nt2 = 0; nt2 < 8; nt2++) {
            int n = nt2 * 8 + qc;
            if (p0r < Pp)
                *(float2*)&Ob[(size_t)p0r * Dd + n] = make_float2(oacc[nt2][0], oacc[nt2][1]);
            if (p1r < Pp)
                *(float2*)&Ob[(size_t)p1r * Dd + n] = make_float2(oacc[nt2][2], oacc[nt2][3]);
        }
    }
}

// ---------------- launch ----------------
extern "C" void kernel_launch(void* const* d_in, const int* in_sizes, int n_in,
                              void* d_out, int out_size) {
    const float* x    = (const float*)d_in[0];
    const float* Wq   = (const float*)d_in[1];
    const float* bq   = (const float*)d_in[2];
    const float* Wk   = (const float*)d_in[3];
    const float* bk   = (const float*)d_in[4];
    const float* Wv   = (const float*)d_in[5];
    const float* bv   = (const float*)d_in[6];
    const float* in_a = (const float*)d_in[7];
    const float* in_b = (const float*)d_in[8];
    const float* at_a = (const float*)d_in[9];
    const float* at_b = (const float*)d_in[10];
    const float* ou_a = (const float*)d_in[11];
    const float* ou_b = (const float*)d_in[12];
    const float* Wt   = (const float*)d_in[13];
    const float* bt   = (const float*)d_in[14];
    const float* pos  = (const float*)d_in[15];
    const float* W1   = (const float*)d_in[16];
    const float* b1   = (const float*)d_in[17];
    const float* W2   = (const float*)d_in[18];
    const float* b2   = (const float*)d_in[19];

    float *pav, *pxres, *pbtsum, *pbqkv;
    __nv_bfloat16 *px2h, *px2l, *pyh, *pyl, *phh, *phl, *pwh, *pwl;
    cudaGetSymbolAddress((void**)&pav,  g_av);
    cudaGetSymbolAddress((void**)&pxres,g_xres);
    cudaGetSymbolAddress((void**)&pbtsum, g_btsum);
    cudaGetSymbolAddress((void**)&pbqkv, g_bqkv);
    cudaGetSymbolAddress((void**)&px2h, g_x2h);
    cudaGetSymbolAddress((void**)&px2l, g_x2l);
    cudaGetSymbolAddress((void**)&pyh,  g_yh);
    cudaGetSymbolAddress((void**)&pyl,  g_yl);
    cudaGetSymbolAddress((void**)&phh,  g_hh);
    cudaGetSymbolAddress((void**)&phl,  g_hl);
    cudaGetSymbolAddress((void**)&pwh,  w_hi);
    cudaGetSymbolAddress((void**)&pwl,  w_lo);

    cudaFuncSetAttribute(attn_mma_k, cudaFuncAttributeMaxDynamicSharedMemorySize,
                         ATT_SMEM);
    cudaFuncSetAttribute(gemm_mma_k, cudaFuncAttributeMaxDynamicSharedMemorySize,
                         GM_SMEM);

    // (0) pre1: LN(x) + QKV weight/bias convert
    pre1_k<<<4248, 256>>>(x, in_a, in_b, Wq, Wk, Wv, bq, bk, bv);
    // (1) merged QKV projection (mode 5), N = 1536
    dim3 gq(1536 / 128, (M1 + 127) / 128);
    gemm_mma_k<<<gq, 256, GM_SMEM>>>(px2h, px2l, pwh + OQ, pwl + OQ, pbqkv, nullptr,
                                     nullptr, nullptr, nullptr, M1, 1536, Dd, 5);
    // (2) pre2: Wt/W1/W2 convert + btsum
    pre2_k<<<16386, 256>>>(Wt, W1, W2, bt);
    // (3) tensor-core attention -> g_av  (ncu capture slot)
    attn_mma_k<<<Bq * (Tt / TG) * Tt * Hh, 256, ATT_SMEM>>>();
    // (4) LN(av)+pos -> y hi/lo
    ln_bf_k<<<ROWS_AV / 8, 256>>>(pav, at_a, at_b, pos, pyh, pyl, POSMOD);
    // (5) tc contraction (mode 1, L2-swizzled 1D grid)
    gemm_mma_k<<<296, 256, GM_SMEM>>>(pyh, pyl, pwh + OT, pwl + OT, pbtsum, x,
                                      pxres, nullptr, nullptr, M1, Dd, Tt * Dd, 1);
    // (6) LN(xres) -> x2 hi/lo
    ln_bf_k<<<M1 / 8, 256>>>(pxres, ou_a, ou_b, nullptr, px2h, px2l, 1);
    // (7) MLP1 (mode 2)
    dim3 g1(2 * Dd / 128, (M1 + 127) / 128);
    gemm_mma_k<<<g1, 256, GM_SMEM>>>(px2h, px2l, pwh + O1, pwl + O1, b1, nullptr,
                                     nullptr, phh, phl, M1, 2 * Dd, Dd, 2);
    // (8) MLP2 (mode 3) -> d_out
    dim3 gtc(Dd / 128, (M1 + 127) / 128);
    gemm_mma_k<<<gtc, 256, GM_SMEM>>>(phh, phl, pwh + O2, pwl + O2, b2, pxres,
                                      (float*)d_out, nullptr, nullptr, M1, Dd, 2 * Dd, 3);
}

// round 15
// speedup vs baseline: 1.3467x; 1.2420x over previous
#include <cuda_runtime.h>
#include <cuda_bf16.h>
#include <math.h>
#include <stdint.h>

#define Bq 4
#define Tt 12
#define Pp 196
#define Dd 512
#define Hh 8
#define DHd 64
#define EPSV 1e-6f

#define M1 (Bq*Tt*Pp)            // 9408
#define ROWS_AV (Bq*Tt*Tt*Pp)    // 112896
#define POSMOD (Tt*Tt*Pp)        // 28224

#define OQ 0
#define OKo 262144
#define OV  524288
#define OT  786432
#define O1  3932160
#define O2  4456448
#define WTOT 4980736

// ---------------- scratch ----------------
__device__ float g_av[(size_t)ROWS_AV*Dd];
__device__ float g_xres[M1*Dd];
__device__ float g_btsum[Dd];
__device__ float g_bqkv[3*Dd];
__device__ __nv_bfloat16 g_x2h[M1*Dd];
__device__ __nv_bfloat16 g_qh[M1*Dd];
__device__ __nv_bfloat16 g_kh[M1*Dd], g_kl[M1*Dd];
__device__ __nv_bfloat16 g_vh[M1*Dd], g_vl[M1*Dd];
__device__ __nv_bfloat16 g_yh[(size_t)ROWS_AV*Dd];
__device__ __nv_bfloat16 g_hh[M1*2*Dd];
__device__ __nv_bfloat16 w_hi[WTOT], w_lo[WTOT];

// ---------------- helpers ----------------
__device__ __forceinline__ float gelu_exact(float x) {
    return 0.5f * x * (1.0f + erff(x * 0.70710678118654752f));
}
__device__ __forceinline__ uint32_t smem_u32(const void* p) {
    uint32_t a;
    asm("{ .reg .u64 t; cvta.to.shared.u64 t, %1; cvt.u32.u64 %0, t; }" : "=r"(a) : "l"(p));
    return a;
}
__device__ __forceinline__ void ldsm4(uint32_t* r, uint32_t a) {
    asm volatile("ldmatrix.sync.aligned.m8n8.x4.shared.b16 {%0,%1,%2,%3}, [%4];"
                 : "=r"(r[0]), "=r"(r[1]), "=r"(r[2]), "=r"(r[3]) : "r"(a));
}
__device__ __forceinline__ void ldsm4t(uint32_t* r, uint32_t a) {
    asm volatile("ldmatrix.sync.aligned.m8n8.x4.trans.shared.b16 {%0,%1,%2,%3}, [%4];"
                 : "=r"(r[0]), "=r"(r[1]), "=r"(r[2]), "=r"(r[3]) : "r"(a));
}
__device__ __forceinline__ void mma_bf16(float* c, const uint32_t* a, uint32_t b0, uint32_t b1) {
    asm volatile(
        "mma.sync.aligned.m16n8k16.row.col.f32.bf16.bf16.f32 "
        "{%0,%1,%2,%3}, {%4,%5,%6,%7}, {%8,%9}, {%0,%1,%2,%3};"
        : "+f"(c[0]), "+f"(c[1]), "+f"(c[2]), "+f"(c[3])
        : "r"(a[0]), "r"(a[1]), "r"(a[2]), "r"(a[3]), "r"(b0), "r"(b1));
}
__device__ __forceinline__ void cpa16(uint32_t s, const void* g) {
    asm volatile("cp.async.cg.shared.global [%0], [%1], 16;" :: "r"(s), "l"(g));
}
#define CPA_COMMIT() asm volatile("cp.async.commit_group;" ::: "memory")
#define CPA_WAIT(n)  asm volatile("cp.async.wait_group %0;" :: "n"(n) : "memory")

__device__ __forceinline__ uint32_t pack_bf16(float a, float b) {
    __nv_bfloat162 t = __floats2bfloat162_rn(a, b);
    return *(uint32_t*)&t;
}
__device__ __forceinline__ void split_store(__nv_bfloat16* hi, __nv_bfloat16* lo,
                                            size_t i, float v) {
    __nv_bfloat16 h = __float2bfloat16(v);
    hi[i] = h;
    lo[i] = __float2bfloat16(v - __bfloat162float(h));
}

// ---------------- LN row body (warp-per-row), hi-only output ----------------
__device__ __forceinline__ void ln_row(const float* __restrict__ in,
                                       const float* __restrict__ al,
                                       const float* __restrict__ be,
                                       const float* __restrict__ pos,
                                       __nv_bfloat16* __restrict__ oh,
                                       int posmod, int row, int lane) {
    const float* rp = in + (size_t)row * Dd;
    float4 v[4];
    float s = 0.f, sq = 0.f;
    #pragma unroll
    for (int j = 0; j < 4; j++) {
        v[j] = *(const float4*)&rp[lane * 4 + j * 128];
        s  += v[j].x + v[j].y + v[j].z + v[j].w;
        sq += v[j].x*v[j].x + v[j].y*v[j].y + v[j].z*v[j].z + v[j].w*v[j].w;
    }
    #pragma unroll
    for (int o = 16; o; o >>= 1) {
        s  += __shfl_xor_sync(0xffffffffu, s,  o);
        sq += __shfl_xor_sync(0xffffffffu, sq, o);
    }
    float mu  = s * (1.0f / Dd);
    float var = (sq - (float)Dd * mu * mu) * (1.0f / (Dd - 1));
    float inv = 1.0f / (sqrtf(fmaxf(var, 0.f)) + EPSV);
    const float* pp = pos ? (pos + (size_t)(row % posmod) * Dd) : nullptr;

    #pragma unroll
    for (int j = 0; j < 4; j++) {
        int c = lane * 4 + j * 128;
        float4 a = *(const float4*)&al[c];
        float4 b = *(const float4*)&be[c];
        float o0 = a.x * (v[j].x - mu) * inv + b.x;
        float o1 = a.y * (v[j].y - mu) * inv + b.y;
        float o2 = a.z * (v[j].z - mu) * inv + b.z;
        float o3 = a.w * (v[j].w - mu) * inv + b.w;
        if (pp) {
            float4 p = *(const float4*)&pp[c];
            o0 += p.x; o1 += p.y; o2 += p.z; o3 += p.w;
        }
        uint2 hv;
        hv.x = pack_bf16(o0, o1);
        hv.y = pack_bf16(o2, o3);
        *(uint2*)&oh[(size_t)row * Dd + c] = hv;
    }
}

// ---------------- LayerNorm standalone ----------------
__global__ void ln_bf_k(const float* __restrict__ in,
                        const float* __restrict__ al,
                        const float* __restrict__ be,
                        const float* __restrict__ pos,
                        __nv_bfloat16* __restrict__ oh,
                        int posmod) {
    int w = threadIdx.x >> 5, lane = threadIdx.x & 31;
    ln_row(in, al, be, pos, oh, posmod, blockIdx.x * 8 + w, lane);
}

// ---------------- pre1: LN(x) + QKV weight/bias convert ----------------
__global__ void pre1_k(const float* __restrict__ x,
                       const float* __restrict__ in_a, const float* __restrict__ in_b,
                       const float* __restrict__ Wq, const float* __restrict__ Wk,
                       const float* __restrict__ Wv,
                       const float* __restrict__ bq, const float* __restrict__ bk,
                       const float* __restrict__ bv) {
    int bid = blockIdx.x, tid = threadIdx.x;
    if (bid < 1176) {
        int w = tid >> 5, lane = tid & 31;
        ln_row(x, in_a, in_b, nullptr, g_x2h, 1, bid * 8 + w, lane);
    } else {
        int i = (bid - 1176) * 256 + tid;
        if (i < 3 * Dd)
            g_bqkv[i] = (i < Dd) ? bq[i] : (i < 2 * Dd) ? bk[i - Dd] : bv[i - 2 * Dd];
        if (i < 786432) {
            int seg = i >> 18, off = i & 262143;
            float v = (seg == 0) ? Wq[off] : (seg == 1) ? Wk[off] : Wv[off];
            split_store(w_hi, w_lo, i, v);
        }
    }
}

// ---------------- pre2: Wt/W1/W2 convert + btsum ----------
__global__ void pre2_k(const float* __restrict__ Wt, const float* __restrict__ W1,
                       const float* __restrict__ W2, const float* __restrict__ bt) {
    int bid = blockIdx.x, tid = threadIdx.x;
    if (bid < 16384) {
        int i = bid * 256 + tid;
        float v; int di;
        if (i < 3145728)      { v = Wt[i];            di = OT + i; }
        else if (i < 3670016) { v = W1[i - 3145728];  di = O1 + (i - 3145728); }
        else                  { v = W2[i - 3670016];  di = O2 + (i - 3670016); }
        split_store(w_hi, w_lo, di, v);
    } else {
        int e = (bid - 16384) * 256 + tid;
        if (e < Dd) {
            float s = 0.f;
            #pragma unroll
            for (int u = 0; u < Tt; u++) s += bt[u * Dd + e];
            g_btsum[e] = s;
        }
    }
}

// ================= mma.sync GEMM: A bf16-hi, B bf16x2 (hi+lo) ======================
// acc = aH*(bH + bL). 2 blocks/SM, 3 smem tiles/stage.
#define LDP 80
#define TILE_B (128*LDP)
#define STAGE_B (3*TILE_B)     // 30720
#define GM_SMEM (2*STAGE_B)    // 61440

__global__ void __launch_bounds__(256, 2) gemm_mma_k(
    const __nv_bfloat16* __restrict__ Ahi,
    const __nv_bfloat16* __restrict__ Bhi, const __nv_bfloat16* __restrict__ Blo,
    const float* __restrict__ bias, const float* __restrict__ res,
    float* __restrict__ Cf, __nv_bfloat16* __restrict__ Chi,
    int M, int N, int K, int mode)
{
    extern __shared__ char smc[];
    int tid = threadIdx.x;
    int wid = tid >> 5, lane = tid & 31;
    int bm, bn;
    if (mode == 1) {
        int bid2 = blockIdx.x;
        int g = bid2 >> 5, r = bid2 & 31;
        int bmi, bni;
        if (g < 9) { bmi = g * 8 + (r & 7); bni = r >> 3; }
        else       { bmi = 72 + (r & 1);    bni = r >> 1; }
        bm = bmi * 128; bn = bni * 128;
    } else {
        bm = blockIdx.y * 128; bn = blockIdx.x * 128;
    }
    int wm = (wid >> 2) * 64;
    int wn = (wid & 3) * 32;

    int lrow = tid >> 1;
    int lhalf = tid & 1;
    int am = min(bm + lrow, M - 1);
    size_t abase;
    if (mode == 1) {
        int b_ = am / (Tt * Pp), r_ = am % (Tt * Pp);
        int t_ = r_ / Pp, p_ = r_ % Pp;
        abase = ((size_t)(b_ * (Tt * Tt) + t_ * Tt) * Pp + p_) * Dd;
    } else {
        abase = (size_t)am * K;
    }
    int brow = bn + lrow;
    uint32_t smrow = lrow * LDP;

    int NC = K / 32;

    auto load_stage = [&](int buf, int c) {
        size_t aoff, boff;
        if (mode == 1) {
            int u = c >> 4, d0 = (c & 15) * 32;
            aoff = abase + (size_t)u * (Pp * Dd) + d0;
            boff = (size_t)u * (Dd * Dd) + (size_t)brow * Dd + d0;
        } else {
            aoff = abase + c * 32;
            boff = (size_t)brow * K + c * 32;
        }
        uint32_t sb = smem_u32(smc) + buf * STAGE_B + smrow;
        #pragma unroll
        for (int i = 0; i < 2; i++) {
            int colk = lhalf * 16 + i * 8;
            uint32_t so = sb + colk * 2;
            cpa16(so,              Ahi + aoff + colk);
            cpa16(so + TILE_B,     Bhi + boff + colk);
            cpa16(so + 2*TILE_B,   Blo + boff + colk);
        }
    };

    int sel = lane >> 3, lr = lane & 7;
    int a_m = wm + (sel & 1) * 8 + lr;
    int b_n = wn + (sel >> 1) * 8 + lr;
    uint32_t smb = smem_u32(smc);
    uint32_t aoffB = a_m * LDP + (sel >> 1) * 16;
    uint32_t boffB = b_n * LDP + (sel & 1) * 16;

    float acc[4][4][4] = {};

    load_stage(0, 0);
    CPA_COMMIT();

    for (int c = 0; c < NC; c++) {
        int buf = c & 1;
        if (c + 1 < NC) {
            load_stage(buf ^ 1, c + 1);
            CPA_COMMIT();
            CPA_WAIT(1);
        } else {
            CPA_WAIT(0);
        }
        __syncthreads();

        uint32_t base = smb + buf * STAGE_B;
        uint32_t aHb = base + aoffB;
        uint32_t bHb = base + TILE_B + boffB;
        uint32_t bLb = base + 2*TILE_B + boffB;

        #pragma unroll
        for (int kk = 0; kk < 2; kk++) {
            uint32_t ko = kk * 32;
            uint32_t bH[2][4], bL[2][4];
            #pragma unroll
            for (int nt2 = 0; nt2 < 2; nt2++) {
                ldsm4(bH[nt2], bHb + nt2 * (16 * LDP) + ko);
                ldsm4(bL[nt2], bLb + nt2 * (16 * LDP) + ko);
            }
            #pragma unroll
            for (int mt = 0; mt < 4; mt++) {
                uint32_t aH[4];
                ldsm4(aH, aHb + mt * (16 * LDP) + ko);
                #pragma unroll
                for (int nt = 0; nt < 4; nt++) {
                    int s2 = nt >> 1, pp = (nt & 1) * 2;
                    mma_bf16(acc[mt][nt], aH, bH[s2][pp], bH[s2][pp+1]);
                }
                #pragma unroll
                for (int nt = 0; nt < 4; nt++) {
                    int s2 = nt >> 1, pp = (nt & 1) * 2;
                    mma_bf16(acc[mt][nt], aH, bL[s2][pp], bL[s2][pp+1]);
                }
            }
        }
        __syncthreads();
    }

    int qrow = lane >> 2;
    int qcol = (lane & 3) * 2;
    #pragma unroll
    for (int mt = 0; mt < 4; mt++) {
        #pragma unroll
        for (int nt = 0; nt < 4; nt++) {
            float* cc = acc[mt][nt];
            int n0 = bn + wn + nt * 8 + qcol;
            float b0 = bias[n0], b1 = bias[n0 + 1];
            #pragma unroll
            for (int hrow = 0; hrow < 2; hrow++) {
                int m = bm + wm + mt * 16 + qrow + hrow * 8;
                if (m >= M) continue;
                float a0 = cc[hrow * 2 + 0];
                float a1 = cc[hrow * 2 + 1];
                float v0, v1;
                if (mode == 0) {
                    size_t off = (size_t)m * N + n0;
                    v0 = a0 + b0; v1 = a1 + b1;
                    *(float2*)&Cf[off] = make_float2(v0, v1);
                } else if (mode == 1) {
                    size_t off = (size_t)m * N + n0;
                    float2 r = *(const float2*)&res[off];
                    v0 = r.x + gelu_exact(a0 * (1.0f / Tt) + b0);
                    v1 = r.y + gelu_exact(a1 * (1.0f / Tt) + b1);
                    *(float2*)&Cf[off] = make_float2(v0, v1);
                } else if (mode == 3) {
                    size_t off = (size_t)m * N + n0;
                    float2 r = *(const float2*)&res[off];
                    v0 = r.x + gelu_exact(a0 + b0);
                    v1 = r.y + gelu_exact(a1 + b1);
                    *(float2*)&Cf[off] = make_float2(v0, v1);
                } else if (mode == 5) {
                    int seg = n0 >> 9, nn = n0 & 511;
                    float g0 = a0 + b0, g1 = a1 + b1;
                    size_t off = (size_t)m * Dd + nn;
                    if (seg == 0) {
                        *(uint32_t*)(g_qh + off) = pack_bf16(g0, g1);
                    } else {
                        __nv_bfloat16* dh = (seg == 1) ? g_kh : g_vh;
                        __nv_bfloat16* dl = (seg == 1) ? g_kl : g_vl;
                        __nv_bfloat16 h0 = __float2bfloat16(g0);
                        __nv_bfloat16 h1 = __float2bfloat16(g1);
                        __nv_bfloat162 hh = __nv_bfloat162(h0, h1);
                        __nv_bfloat162 ll = __floats2bfloat162_rn(g0 - __bfloat162float(h0),
                                                                  g1 - __bfloat162float(h1));
                        *(__nv_bfloat162*)(dh + off) = hh;
                        *(__nv_bfloat162*)(dl + off) = ll;
                    }
                } else { // mode 2: h hi only
                    size_t off = (size_t)m * N + n0;
                    float g0 = gelu_exact(a0 + b0);
                    float g1 = gelu_exact(a1 + b1);
                    *(uint32_t*)(Chi + off) = pack_bf16(g0, g1);
                }
            }
        }
    }
}

// ================= tensor-core attention — precision-trimmed (unchanged) =====
#define AKR 208
#define ALD 144
#define ASM_ONE (AKR*ALD)
#define ATT_SMEM (4*ASM_ONE)
#define TG 4

__global__ void __launch_bounds__(256, 1) attn_mma_k() {
    int bid = blockIdx.x;
    int h = bid & 7;
    int u = (bid >> 3) % Tt;
    int tg = (bid / (8 * Tt)) % (Tt / TG);
    int b = bid / (8 * Tt * (Tt / TG));

    extern __shared__ char smb_[];
    uint32_t skh = smem_u32(smb_);
    uint32_t skl = skh + ASM_ONE;
    uint32_t svh = skh + 2 * ASM_ONE;
    uint32_t svl = skh + 3 * ASM_ONE;

    int tid = threadIdx.x;
    int w = tid >> 5, lane = tid & 31;

    size_t kvbase = ((size_t)(b * Tt + u) * Pp) * Dd + h * DHd;

    for (int idx = tid; idx < AKR * 8; idx += 256) {
        int row = idx >> 3, seg = idx & 7;
        uint4 kh4 = make_uint4(0,0,0,0), kl4 = kh4, vh4 = kh4, vl4 = kh4;
        if (row < Pp) {
            size_t g = kvbase + (size_t)row * Dd + seg * 8;
            kh4 = *(const uint4*)&g_kh[g];
            kl4 = *(const uint4*)&g_kl[g];
            vh4 = *(const uint4*)&g_vh[g];
            vl4 = *(const uint4*)&g_vl[g];
        }
        uint32_t so = row * ALD + seg * 16;
        *(uint4*)(smb_ + so) = kh4;
        *(uint4*)(smb_ + ASM_ONE + so) = kl4;
        *(uint4*)(smb_ + 2*ASM_ONE + so) = vh4;
        *(uint4*)(smb_ + 3*ASM_ONE + so) = vl4;
    }
    __syncthreads();

    int gr = lane >> 2, qc = (lane & 3) * 2;
    int sel = lane >> 3, lr = lane & 7;
    uint32_t koff = ((sel >> 1) * 8 + lr) * ALD + (sel & 1) * 16;
    uint32_t voff = ((sel & 1) * 8 + lr) * ALD + (sel >> 1) * 16;

    for (int tau = w; tau < 13 * TG; tau += 8) {
        int tl = tau / 13, mt = tau % 13;
        int t = tg * TG + tl;
        size_t qbase = ((size_t)(b * Tt + t) * Pp) * Dd + h * DHd;
        float* Ob = g_av + ((size_t)((b * Tt + t) * Tt + u) * Pp) * Dd + h * DHd;

        int m0 = mt * 16;
        int r0 = min(m0 + gr, Pp - 1);
        int r1 = min(m0 + gr + 8, Pp - 1);

        uint32_t qa_h[4][4];
        #pragma unroll
        for (int J = 0; J < 4; J++) {
            int c0 = J * 16 + qc;
            qa_h[J][0] = *(const uint32_t*)&g_qh[qbase + (size_t)r0 * Dd + c0];
            qa_h[J][1] = *(const uint32_t*)&g_qh[qbase + (size_t)r1 * Dd + c0];
            qa_h[J][2] = *(const uint32_t*)&g_qh[qbase + (size_t)r0 * Dd + c0 + 8];
            qa_h[J][3] = *(const uint32_t*)&g_qh[qbase + (size_t)r1 * Dd + c0 + 8];
        }

        float sc[26][4];
        #pragma unroll
        for (int nt = 0; nt < 26; nt++)
            #pragma unroll
            for (int i = 0; i < 4; i++) sc[nt][i] = 0.f;

        #pragma unroll
        for (int J = 0; J < 4; J++) {
            for (int ntp = 0; ntp < 12; ntp += 2) {
                uint32_t kb0 = ntp * (16 * ALD) + koff + J * 32;
                uint32_t kb1 = kb0 + 16 * ALD;
                uint32_t bh0[4], bl0[4], bh1[4], bl1[4];
                ldsm4(bh0, skh + kb0);
                ldsm4(bl0, skl + kb0);
                ldsm4(bh1, skh + kb1);
                ldsm4(bl1, skl + kb1);
                mma_bf16(sc[2*ntp],   qa_h[J], bh0[0], bh0[1]);
                mma_bf16(sc[2*ntp+1], qa_h[J], bh0[2], bh0[3]);
                mma_bf16(sc[2*ntp+2], qa_h[J], bh1[0], bh1[1]);
                mma_bf16(sc[2*ntp+3], qa_h[J], bh1[2], bh1[3]);
                mma_bf16(sc[2*ntp],   qa_h[J], bl0[0], bl0[1]);
                mma_bf16(sc[2*ntp+1], qa_h[J], bl0[2], bl0[3]);
                mma_bf16(sc[2*ntp+2], qa_h[J], bl1[0], bl1[1]);
                mma_bf16(sc[2*ntp+3], qa_h[J], bl1[2], bl1[3]);
            }
            {
                uint32_t kb = 12 * (16 * ALD) + koff + J * 32;
                uint32_t bh[4], bl[4];
                ldsm4(bh, skh + kb);
                ldsm4(bl, skl + kb);
                mma_bf16(sc[24], qa_h[J], bh[0], bh[1]);
                mma_bf16(sc[25], qa_h[J], bh[2], bh[3]);
                mma_bf16(sc[24], qa_h[J], bl[0], bl[1]);
                mma_bf16(sc[25], qa_h[J], bl[2], bl[3]);
            }
        }

        float mx0 = -1e30f, mx1 = -1e30f;
        #pragma unroll
        for (int nt = 0; nt < 26; nt++) {
            int n0 = nt * 8 + qc;
            if (n0 >= Pp) {
                sc[nt][0] = sc[nt][1] = sc[nt][2] = sc[nt][3] = -1e30f;
            } else {
                sc[nt][0] *= 0.125f; sc[nt][1] *= 0.125f;
                sc[nt][2] *= 0.125f; sc[nt][3] *= 0.125f;
            }
            mx0 = fmaxf(mx0, fmaxf(sc[nt][0], sc[nt][1]));
            mx1 = fmaxf(mx1, fmaxf(sc[nt][2], sc[nt][3]));
        }
        mx0 = fmaxf(mx0, __shfl_xor_sync(0xffffffffu, mx0, 1));
        mx0 = fmaxf(mx0, __shfl_xor_sync(0xffffffffu, mx0, 2));
        mx1 = fmaxf(mx1, __shfl_xor_sync(0xffffffffu, mx1, 1));
        mx1 = fmaxf(mx1, __shfl_xor_sync(0xffffffffu, mx1, 2));
        float sum0 = 0.f, sum1 = 0.f;
        #pragma unroll
        for (int nt = 0; nt < 26; nt++) {
            sc[nt][0] = __expf(sc[nt][0] - mx0);
            sc[nt][1] = __expf(sc[nt][1] - mx0);
            sc[nt][2] = __expf(sc[nt][2] - mx1);
            sc[nt][3] = __expf(sc[nt][3] - mx1);
            sum0 += sc[nt][0] + sc[nt][1];
            sum1 += sc[nt][2] + sc[nt][3];
        }
        sum0 += __shfl_xor_sync(0xffffffffu, sum0, 1);
        sum0 += __shfl_xor_sync(0xffffffffu, sum0, 2);
        sum1 += __shfl_xor_sync(0xffffffffu, sum1, 1);
        sum1 += __shfl_xor_sync(0xffffffffu, sum1, 2);
        float rv0 = 1.0f / sum0, rv1 = 1.0f / sum1;
        #pragma unroll
        for (int nt = 0; nt < 26; nt++) {
            sc[nt][0] *= rv0; sc[nt][1] *= rv0;
            sc[nt][2] *= rv1; sc[nt][3] *= rv1;
        }

        float oacc[8][4];
        #pragma unroll
        for (int i = 0; i < 8; i++)
            #pragma unroll
            for (int jx = 0; jx < 4; jx++) oacc[i][jx] = 0.f;

        for (int J = 0; J < 13; J++) {
            uint32_t pa_h[4];
            pa_h[0] = pack_bf16(sc[2*J][0],   sc[2*J][1]);
            pa_h[1] = pack_bf16(sc[2*J][2],   sc[2*J][3]);
            pa_h[2] = pack_bf16(sc[2*J+1][0], sc[2*J+1][1]);
            pa_h[3] = pack_bf16(sc[2*J+1][2], sc[2*J+1][3]);

            uint32_t vb = J * (16 * ALD) + voff;
            uint32_t bh[4][4], bl[4][4];
            #pragma unroll
            for (int np = 0; np < 4; np++) {
                ldsm4t(bh[np], svh + vb + np * 32);
                ldsm4t(bl[np], svl + vb + np * 32);
            }
            #pragma unroll
            for (int np = 0; np < 4; np++) {
                mma_bf16(oacc[2*np],   pa_h, bh[np][0], bh[np][1]);
                mma_bf16(oacc[2*np+1], pa_h, bh[np][2], bh[np][3]);
            }
            #pragma unroll
            for (int np = 0; np < 4; np++) {
                mma_bf16(oacc[2*np],   pa_h, bl[np][0], bl[np][1]);
                mma_bf16(oacc[2*np+1], pa_h, bl[np][2], bl[np][3]);
            }
        }

        int p0r = m0 + gr, p1r = m0 + gr + 8;
        #pragma unroll
        for (int nt2 = 0; nt2 < 8; nt2++) {
            int n = nt2 * 8 + qc;
            if (p0r < Pp)
                *(float2*)&Ob[(size_t)p0r * Dd + n] = make_float2(oacc[nt2][0], oacc[nt2][1]);
            if (p1r < Pp)
                *(float2*)&Ob[(size_t)p1r * Dd + n] = make_float2(oacc[nt2][2], oacc[nt2][3]);
        }
    }
}

// ---------------- launch ----------------
extern "C" void kernel_launch(void* const* d_in, const int* in_sizes, int n_in,
                              void* d_out, int out_size) {
    const float* x    = (const float*)d_in[0];
    const float* Wq   = (const float*)d_in[1];
    const float* bq   = (const float*)d_in[2];
    const float* Wk   = (const float*)d_in[3];
    const float* bk   = (const float*)d_in[4];
    const float* Wv   = (const float*)d_in[5];
    const float* bv   = (const float*)d_in[6];
    const float* in_a = (const float*)d_in[7];
    const float* in_b = (const float*)d_in[8];
    const float* at_a = (const float*)d_in[9];
    const float* at_b = (const float*)d_in[10];
    const float* ou_a = (const float*)d_in[11];
    const float* ou_b = (const float*)d_in[12];
    const float* Wt   = (const float*)d_in[13];
    const float* bt   = (const float*)d_in[14];
    const float* pos  = (const float*)d_in[15];
    const float* W1   = (const float*)d_in[16];
    const float* b1   = (const float*)d_in[17];
    const float* W2   = (const float*)d_in[18];
    const float* b2   = (const float*)d_in[19];

    float *pav, *pxres, *pbtsum, *pbqkv;
    __nv_bfloat16 *px2h, *pyh, *phh, *pwh, *pwl;
    cudaGetSymbolAddress((void**)&pav,  g_av);
    cudaGetSymbolAddress((void**)&pxres,g_xres);
    cudaGetSymbolAddress((void**)&pbtsum, g_btsum);
    cudaGetSymbolAddress((void**)&pbqkv, g_bqkv);
    cudaGetSymbolAddress((void**)&px2h, g_x2h);
    cudaGetSymbolAddress((void**)&pyh,  g_yh);
    cudaGetSymbolAddress((void**)&phh,  g_hh);
    cudaGetSymbolAddress((void**)&pwh,  w_hi);
    cudaGetSymbolAddress((void**)&pwl,  w_lo);

    cudaFuncSetAttribute(attn_mma_k, cudaFuncAttributeMaxDynamicSharedMemorySize,
                         ATT_SMEM);
    cudaFuncSetAttribute(gemm_mma_k, cudaFuncAttributeMaxDynamicSharedMemorySize,
                         GM_SMEM);

    // (0) pre1: LN(x) + QKV weight/bias convert
    pre1_k<<<4248, 256>>>(x, in_a, in_b, Wq, Wk, Wv, bq, bk, bv);
    // (1) merged QKV projection (mode 5), N = 1536
    dim3 gq(1536 / 128, (M1 + 127) / 128);
    gemm_mma_k<<<gq, 256, GM_SMEM>>>(px2h, pwh + OQ, pwl + OQ, pbqkv, nullptr,
                                     nullptr, nullptr, M1, 1536, Dd, 5);
    // (2) pre2: Wt/W1/W2 convert + btsum
    pre2_k<<<16386, 256>>>(Wt, W1, W2, bt);
    // (3) tensor-core attention -> g_av  (ncu capture slot)
    attn_mma_k<<<Bq * (Tt / TG) * Tt * Hh, 256, ATT_SMEM>>>();
    // (4) LN(av)+pos -> y hi
    ln_bf_k<<<ROWS_AV / 8, 256>>>(pav, at_a, at_b, pos, pyh, POSMOD);
    // (5) tc contraction (mode 1, L2-swizzled 1D grid)
    gemm_mma_k<<<296, 256, GM_SMEM>>>(pyh, pwh + OT, pwl + OT, pbtsum, x,
                                      pxres, nullptr, M1, Dd, Tt * Dd, 1);
    // (6) LN(xres) -> x2 hi
    ln_bf_k<<<M1 / 8, 256>>>(pxres, ou_a, ou_b, nullptr, px2h, 1);
    // (7) MLP1 (mode 2)
    dim3 g1(2 * Dd / 128, (M1 + 127) / 128);
    gemm_mma_k<<<g1, 256, GM_SMEM>>>(px2h, pwh + O1, pwl + O1, b1, nullptr,
                                     nullptr, phh, M1, 2 * Dd, Dd, 2);
    // (8) MLP2 (mode 3) -> d_out
    dim3 gtc(Dd / 128, (M1 + 127) / 128);
    gemm_mma_k<<<gtc, 256, GM_SMEM>>>(phh, pwh + O2, pwl + O2, b2, pxres,
                                      (float*)d_out, nullptr, M1, Dd, 2 * Dd, 3);
}

// round 16
// speedup vs baseline: 1.5028x; 1.1159x over previous
#include <cuda_runtime.h>
#include <cuda_bf16.h>
#include <math.h>
#include <stdint.h>

#define Bq 4
#define Tt 12
#define Pp 196
#define Dd 512
#define Hh 8
#define DHd 64
#define EPSV 1e-6f

#define M1 (Bq*Tt*Pp)            // 9408
#define ROWS_AV (Bq*Tt*Tt*Pp)    // 112896
#define POSMOD (Tt*Tt*Pp)        // 28224

#define OQ 0
#define OKo 262144
#define OV  524288
#define OT  786432
#define O1  3932160
#define O2  4456448
#define WTOT 4980736

// ---------------- scratch ----------------
__device__ float g_av[(size_t)ROWS_AV*Dd];
__device__ float g_xres[M1*Dd];
__device__ float g_btsum[Dd];
__device__ float g_bqkv[3*Dd];
__device__ __nv_bfloat16 g_x2h[M1*Dd];
__device__ __nv_bfloat16 g_qh[M1*Dd];
__device__ __nv_bfloat16 g_kh[M1*Dd];
__device__ __nv_bfloat16 g_vh[M1*Dd];
__device__ __nv_bfloat16 g_yh[(size_t)ROWS_AV*Dd];
__device__ __nv_bfloat16 g_hh[M1*2*Dd];
__device__ __nv_bfloat16 w_hi[WTOT], w_lo[WTOT];

// ---------------- helpers ----------------
__device__ __forceinline__ float gelu_exact(float x) {
    return 0.5f * x * (1.0f + erff(x * 0.70710678118654752f));
}
__device__ __forceinline__ uint32_t smem_u32(const void* p) {
    uint32_t a;
    asm("{ .reg .u64 t; cvta.to.shared.u64 t, %1; cvt.u32.u64 %0, t; }" : "=r"(a) : "l"(p));
    return a;
}
__device__ __forceinline__ void ldsm4(uint32_t* r, uint32_t a) {
    asm volatile("ldmatrix.sync.aligned.m8n8.x4.shared.b16 {%0,%1,%2,%3}, [%4];"
                 : "=r"(r[0]), "=r"(r[1]), "=r"(r[2]), "=r"(r[3]) : "r"(a));
}
__device__ __forceinline__ void ldsm4t(uint32_t* r, uint32_t a) {
    asm volatile("ldmatrix.sync.aligned.m8n8.x4.trans.shared.b16 {%0,%1,%2,%3}, [%4];"
                 : "=r"(r[0]), "=r"(r[1]), "=r"(r[2]), "=r"(r[3]) : "r"(a));
}
__device__ __forceinline__ void mma_bf16(float* c, const uint32_t* a, uint32_t b0, uint32_t b1) {
    asm volatile(
        "mma.sync.aligned.m16n8k16.row.col.f32.bf16.bf16.f32 "
        "{%0,%1,%2,%3}, {%4,%5,%6,%7}, {%8,%9}, {%0,%1,%2,%3};"
        : "+f"(c[0]), "+f"(c[1]), "+f"(c[2]), "+f"(c[3])
        : "r"(a[0]), "r"(a[1]), "r"(a[2]), "r"(a[3]), "r"(b0), "r"(b1));
}
__device__ __forceinline__ void cpa16(uint32_t s, const void* g) {
    asm volatile("cp.async.cg.shared.global [%0], [%1], 16;" :: "r"(s), "l"(g));
}
#define CPA_COMMIT() asm volatile("cp.async.commit_group;" ::: "memory")
#define CPA_WAIT(n)  asm volatile("cp.async.wait_group %0;" :: "n"(n) : "memory")

__device__ __forceinline__ uint32_t pack_bf16(float a, float b) {
    __nv_bfloat162 t = __floats2bfloat162_rn(a, b);
    return *(uint32_t*)&t;
}
__device__ __forceinline__ void split_store(__nv_bfloat16* hi, __nv_bfloat16* lo,
                                            size_t i, float v) {
    __nv_bfloat16 h = __float2bfloat16(v);
    hi[i] = h;
    lo[i] = __float2bfloat16(v - __bfloat162float(h));
}

// ---------------- LN row body (warp-per-row), hi-only output ----------------
__device__ __forceinline__ void ln_row(const float* __restrict__ in,
                                       const float* __restrict__ al,
                                       const float* __restrict__ be,
                                       const float* __restrict__ pos,
                                       __nv_bfloat16* __restrict__ oh,
                                       int posmod, int row, int lane) {
    const float* rp = in + (size_t)row * Dd;
    float4 v[4];
    float s = 0.f, sq = 0.f;
    #pragma unroll
    for (int j = 0; j < 4; j++) {
        v[j] = *(const float4*)&rp[lane * 4 + j * 128];
        s  += v[j].x + v[j].y + v[j].z + v[j].w;
        sq += v[j].x*v[j].x + v[j].y*v[j].y + v[j].z*v[j].z + v[j].w*v[j].w;
    }
    #pragma unroll
    for (int o = 16; o; o >>= 1) {
        s  += __shfl_xor_sync(0xffffffffu, s,  o);
        sq += __shfl_xor_sync(0xffffffffu, sq, o);
    }
    float mu  = s * (1.0f / Dd);
    float var = (sq - (float)Dd * mu * mu) * (1.0f / (Dd - 1));
    float inv = 1.0f / (sqrtf(fmaxf(var, 0.f)) + EPSV);
    const float* pp = pos ? (pos + (size_t)(row % posmod) * Dd) : nullptr;

    #pragma unroll
    for (int j = 0; j < 4; j++) {
        int c = lane * 4 + j * 128;
        float4 a = *(const float4*)&al[c];
        float4 b = *(const float4*)&be[c];
        float o0 = a.x * (v[j].x - mu) * inv + b.x;
        float o1 = a.y * (v[j].y - mu) * inv + b.y;
        float o2 = a.z * (v[j].z - mu) * inv + b.z;
        float o3 = a.w * (v[j].w - mu) * inv + b.w;
        if (pp) {
            float4 p = *(const float4*)&pp[c];
            o0 += p.x; o1 += p.y; o2 += p.z; o3 += p.w;
        }
        uint2 hv;
        hv.x = pack_bf16(o0, o1);
        hv.y = pack_bf16(o2, o3);
        *(uint2*)&oh[(size_t)row * Dd + c] = hv;
    }
}

// ---------------- LayerNorm standalone ----------------
__global__ void ln_bf_k(const float* __restrict__ in,
                        const float* __restrict__ al,
                        const float* __restrict__ be,
                        const float* __restrict__ pos,
                        __nv_bfloat16* __restrict__ oh,
                        int posmod) {
    int w = threadIdx.x >> 5, lane = threadIdx.x & 31;
    ln_row(in, al, be, pos, oh, posmod, blockIdx.x * 8 + w, lane);
}

// ---------------- pre1: LN(x) + QKV weight/bias convert ----------------
__global__ void pre1_k(const float* __restrict__ x,
                       const float* __restrict__ in_a, const float* __restrict__ in_b,
                       const float* __restrict__ Wq, const float* __restrict__ Wk,
                       const float* __restrict__ Wv,
                       const float* __restrict__ bq, const float* __restrict__ bk,
                       const float* __restrict__ bv) {
    int bid = blockIdx.x, tid = threadIdx.x;
    if (bid < 1176) {
        int w = tid >> 5, lane = tid & 31;
        ln_row(x, in_a, in_b, nullptr, g_x2h, 1, bid * 8 + w, lane);
    } else {
        int i = (bid - 1176) * 256 + tid;
        if (i < 3 * Dd)
            g_bqkv[i] = (i < Dd) ? bq[i] : (i < 2 * Dd) ? bk[i - Dd] : bv[i - 2 * Dd];
        if (i < 786432) {
            int seg = i >> 18, off = i & 262143;
            float v = (seg == 0) ? Wq[off] : (seg == 1) ? Wk[off] : Wv[off];
            split_store(w_hi, w_lo, i, v);
        }
    }
}

// ---------------- pre2: Wt/W1/W2 convert + btsum ----------
__global__ void pre2_k(const float* __restrict__ Wt, const float* __restrict__ W1,
                       const float* __restrict__ W2, const float* __restrict__ bt) {
    int bid = blockIdx.x, tid = threadIdx.x;
    if (bid < 16384) {
        int i = bid * 256 + tid;
        float v; int di;
        if (i < 3145728)      { v = Wt[i];            di = OT + i; }
        else if (i < 3670016) { v = W1[i - 3145728];  di = O1 + (i - 3145728); }
        else                  { v = W2[i - 3670016];  di = O2 + (i - 3670016); }
        split_store(w_hi, w_lo, di, v);
    } else {
        int e = (bid - 16384) * 256 + tid;
        if (e < Dd) {
            float s = 0.f;
            #pragma unroll
            for (int u = 0; u < Tt; u++) s += bt[u * Dd + e];
            g_btsum[e] = s;
        }
    }
}

// ================= mma.sync GEMM: A bf16-hi, B bf16x2 (hi+lo) ======================
#define LDP 80
#define TILE_B (128*LDP)
#define STAGE_B (3*TILE_B)
#define GM_SMEM (2*STAGE_B)

__global__ void __launch_bounds__(256, 2) gemm_mma_k(
    const __nv_bfloat16* __restrict__ Ahi,
    const __nv_bfloat16* __restrict__ Bhi, const __nv_bfloat16* __restrict__ Blo,
    const float* __restrict__ bias, const float* __restrict__ res,
    float* __restrict__ Cf, __nv_bfloat16* __restrict__ Chi,
    int M, int N, int K, int mode)
{
    extern __shared__ char smc[];
    int tid = threadIdx.x;
    int wid = tid >> 5, lane = tid & 31;
    int bm, bn;
    if (mode == 1) {
        int bid2 = blockIdx.x;
        int g = bid2 >> 5, r = bid2 & 31;
        int bmi, bni;
        if (g < 9) { bmi = g * 8 + (r & 7); bni = r >> 3; }
        else       { bmi = 72 + (r & 1);    bni = r >> 1; }
        bm = bmi * 128; bn = bni * 128;
    } else {
        bm = blockIdx.y * 128; bn = blockIdx.x * 128;
    }
    int wm = (wid >> 2) * 64;
    int wn = (wid & 3) * 32;

    int lrow = tid >> 1;
    int lhalf = tid & 1;
    int am = min(bm + lrow, M - 1);
    size_t abase;
    if (mode == 1) {
        int b_ = am / (Tt * Pp), r_ = am % (Tt * Pp);
        int t_ = r_ / Pp, p_ = r_ % Pp;
        abase = ((size_t)(b_ * (Tt * Tt) + t_ * Tt) * Pp + p_) * Dd;
    } else {
        abase = (size_t)am * K;
    }
    int brow = bn + lrow;
    uint32_t smrow = lrow * LDP;

    int NC = K / 32;

    auto load_stage = [&](int buf, int c) {
        size_t aoff, boff;
        if (mode == 1) {
            int u = c >> 4, d0 = (c & 15) * 32;
            aoff = abase + (size_t)u * (Pp * Dd) + d0;
            boff = (size_t)u * (Dd * Dd) + (size_t)brow * Dd + d0;
        } else {
            aoff = abase + c * 32;
            boff = (size_t)brow * K + c * 32;
        }
        uint32_t sb = smem_u32(smc) + buf * STAGE_B + smrow;
        #pragma unroll
        for (int i = 0; i < 2; i++) {
            int colk = lhalf * 16 + i * 8;
            uint32_t so = sb + colk * 2;
            cpa16(so,              Ahi + aoff + colk);
            cpa16(so + TILE_B,     Bhi + boff + colk);
            cpa16(so + 2*TILE_B,   Blo + boff + colk);
        }
    };

    int sel = lane >> 3, lr = lane & 7;
    int a_m = wm + (sel & 1) * 8 + lr;
    int b_n = wn + (sel >> 1) * 8 + lr;
    uint32_t smb = smem_u32(smc);
    uint32_t aoffB = a_m * LDP + (sel >> 1) * 16;
    uint32_t boffB = b_n * LDP + (sel & 1) * 16;

    float acc[4][4][4] = {};

    load_stage(0, 0);
    CPA_COMMIT();

    for (int c = 0; c < NC; c++) {
        int buf = c & 1;
        if (c + 1 < NC) {
            load_stage(buf ^ 1, c + 1);
            CPA_COMMIT();
            CPA_WAIT(1);
        } else {
            CPA_WAIT(0);
        }
        __syncthreads();

        uint32_t base = smb + buf * STAGE_B;
        uint32_t aHb = base + aoffB;
        uint32_t bHb = base + TILE_B + boffB;
        uint32_t bLb = base + 2*TILE_B + boffB;

        #pragma unroll
        for (int kk = 0; kk < 2; kk++) {
            uint32_t ko = kk * 32;
            uint32_t bH[2][4], bL[2][4];
            #pragma unroll
            for (int nt2 = 0; nt2 < 2; nt2++) {
                ldsm4(bH[nt2], bHb + nt2 * (16 * LDP) + ko);
                ldsm4(bL[nt2], bLb + nt2 * (16 * LDP) + ko);
            }
            #pragma unroll
            for (int mt = 0; mt < 4; mt++) {
                uint32_t aH[4];
                ldsm4(aH, aHb + mt * (16 * LDP) + ko);
                #pragma unroll
                for (int nt = 0; nt < 4; nt++) {
                    int s2 = nt >> 1, pp = (nt & 1) * 2;
                    mma_bf16(acc[mt][nt], aH, bH[s2][pp], bH[s2][pp+1]);
                }
                #pragma unroll
                for (int nt = 0; nt < 4; nt++) {
                    int s2 = nt >> 1, pp = (nt & 1) * 2;
                    mma_bf16(acc[mt][nt], aH, bL[s2][pp], bL[s2][pp+1]);
                }
            }
        }
        __syncthreads();
    }

    int qrow = lane >> 2;
    int qcol = (lane & 3) * 2;
    #pragma unroll
    for (int mt = 0; mt < 4; mt++) {
        #pragma unroll
        for (int nt = 0; nt < 4; nt++) {
            float* cc = acc[mt][nt];
            int n0 = bn + wn + nt * 8 + qcol;
            float b0 = bias[n0], b1 = bias[n0 + 1];
            #pragma unroll
            for (int hrow = 0; hrow < 2; hrow++) {
                int m = bm + wm + mt * 16 + qrow + hrow * 8;
                if (m >= M) continue;
                float a0 = cc[hrow * 2 + 0];
                float a1 = cc[hrow * 2 + 1];
                float v0, v1;
                if (mode == 0) {
                    size_t off = (size_t)m * N + n0;
                    v0 = a0 + b0; v1 = a1 + b1;
                    *(float2*)&Cf[off] = make_float2(v0, v1);
                } else if (mode == 1) {
                    size_t off = (size_t)m * N + n0;
                    float2 r = *(const float2*)&res[off];
                    v0 = r.x + gelu_exact(a0 * (1.0f / Tt) + b0);
                    v1 = r.y + gelu_exact(a1 * (1.0f / Tt) + b1);
                    *(float2*)&Cf[off] = make_float2(v0, v1);
                } else if (mode == 3) {
                    size_t off = (size_t)m * N + n0;
                    float2 r = *(const float2*)&res[off];
                    v0 = r.x + gelu_exact(a0 + b0);
                    v1 = r.y + gelu_exact(a1 + b1);
                    *(float2*)&Cf[off] = make_float2(v0, v1);
                } else if (mode == 5) {
                    int seg = n0 >> 9, nn = n0 & 511;
                    float g0 = a0 + b0, g1 = a1 + b1;
                    size_t off = (size_t)m * Dd + nn;
                    __nv_bfloat16* dh = (seg == 0) ? g_qh : (seg == 1) ? g_kh : g_vh;
                    *(uint32_t*)(dh + off) = pack_bf16(g0, g1);
                } else { // mode 2
                    size_t off = (size_t)m * N + n0;
                    float g0 = gelu_exact(a0 + b0);
                    float g1 = gelu_exact(a1 + b1);
                    *(uint32_t*)(Chi + off) = pack_bf16(g0, g1);
                }
            }
        }
    }
}

// ================= tensor-core attention — pure bf16 =====
// QK: q_hi*k_hi ; PV: p_hi*v_hi. K/V hi-only smem (2 tiles).
#define AKR 208
#define ALD 144
#define ASM_ONE (AKR*ALD)
#define ATT_SMEM (2*ASM_ONE)
#define TG 4

__global__ void __launch_bounds__(256, 1) attn_mma_k() {
    int bid = blockIdx.x;
    int h = bid & 7;
    int u = (bid >> 3) % Tt;
    int tg = (bid / (8 * Tt)) % (Tt / TG);
    int b = bid / (8 * Tt * (Tt / TG));

    extern __shared__ char smb_[];
    uint32_t skh = smem_u32(smb_);
    uint32_t svh = skh + ASM_ONE;

    int tid = threadIdx.x;
    int w = tid >> 5, lane = tid & 31;

    size_t kvbase = ((size_t)(b * Tt + u) * Pp) * Dd + h * DHd;

    for (int idx = tid; idx < AKR * 8; idx += 256) {
        int row = idx >> 3, seg = idx & 7;
        uint4 kh4 = make_uint4(0,0,0,0), vh4 = kh4;
        if (row < Pp) {
            size_t g = kvbase + (size_t)row * Dd + seg * 8;
            kh4 = *(const uint4*)&g_kh[g];
            vh4 = *(const uint4*)&g_vh[g];
        }
        uint32_t so = row * ALD + seg * 16;
        *(uint4*)(smb_ + so) = kh4;
        *(uint4*)(smb_ + ASM_ONE + so) = vh4;
    }
    __syncthreads();

    int gr = lane >> 2, qc = (lane & 3) * 2;
    int sel = lane >> 3, lr = lane & 7;
    uint32_t koff = ((sel >> 1) * 8 + lr) * ALD + (sel & 1) * 16;
    uint32_t voff = ((sel & 1) * 8 + lr) * ALD + (sel >> 1) * 16;

    for (int tau = w; tau < 13 * TG; tau += 8) {
        int tl = tau / 13, mt = tau % 13;
        int t = tg * TG + tl;
        size_t qbase = ((size_t)(b * Tt + t) * Pp) * Dd + h * DHd;
        float* Ob = g_av + ((size_t)((b * Tt + t) * Tt + u) * Pp) * Dd + h * DHd;

        int m0 = mt * 16;
        int r0 = min(m0 + gr, Pp - 1);
        int r1 = min(m0 + gr + 8, Pp - 1);

        uint32_t qa_h[4][4];
        #pragma unroll
        for (int J = 0; J < 4; J++) {
            int c0 = J * 16 + qc;
            qa_h[J][0] = *(const uint32_t*)&g_qh[qbase + (size_t)r0 * Dd + c0];
            qa_h[J][1] = *(const uint32_t*)&g_qh[qbase + (size_t)r1 * Dd + c0];
            qa_h[J][2] = *(const uint32_t*)&g_qh[qbase + (size_t)r0 * Dd + c0 + 8];
            qa_h[J][3] = *(const uint32_t*)&g_qh[qbase + (size_t)r1 * Dd + c0 + 8];
        }

        float sc[26][4];
        #pragma unroll
        for (int nt = 0; nt < 26; nt++)
            #pragma unroll
            for (int i = 0; i < 4; i++) sc[nt][i] = 0.f;

        #pragma unroll
        for (int J = 0; J < 4; J++) {
            for (int ntp = 0; ntp < 12; ntp += 2) {
                uint32_t kb0 = ntp * (16 * ALD) + koff + J * 32;
                uint32_t kb1 = kb0 + 16 * ALD;
                uint32_t bh0[4], bh1[4];
                ldsm4(bh0, skh + kb0);
                ldsm4(bh1, skh + kb1);
                mma_bf16(sc[2*ntp],   qa_h[J], bh0[0], bh0[1]);
                mma_bf16(sc[2*ntp+1], qa_h[J], bh0[2], bh0[3]);
                mma_bf16(sc[2*ntp+2], qa_h[J], bh1[0], bh1[1]);
                mma_bf16(sc[2*ntp+3], qa_h[J], bh1[2], bh1[3]);
            }
            {
                uint32_t kb = 12 * (16 * ALD) + koff + J * 32;
                uint32_t bh[4];
                ldsm4(bh, skh + kb);
                mma_bf16(sc[24], qa_h[J], bh[0], bh[1]);
                mma_bf16(sc[25], qa_h[J], bh[2], bh[3]);
            }
        }

        float mx0 = -1e30f, mx1 = -1e30f;
        #pragma unroll
        for (int nt = 0; nt < 26; nt++) {
            int n0 = nt * 8 + qc;
            if (n0 >= Pp) {
                sc[nt][0] = sc[nt][1] = sc[nt][2] = sc[nt][3] = -1e30f;
            } else {
                sc[nt][0] *= 0.125f; sc[nt][1] *= 0.125f;
                sc[nt][2] *= 0.125f; sc[nt][3] *= 0.125f;
            }
            mx0 = fmaxf(mx0, fmaxf(sc[nt][0], sc[nt][1]));
            mx1 = fmaxf(mx1, fmaxf(sc[nt][2], sc[nt][3]));
        }
        mx0 = fmaxf(mx0, __shfl_xor_sync(0xffffffffu, mx0, 1));
        mx0 = fmaxf(mx0, __shfl_xor_sync(0xffffffffu, mx0, 2));
        mx1 = fmaxf(mx1, __shfl_xor_sync(0xffffffffu, mx1, 1));
        mx1 = fmaxf(mx1, __shfl_xor_sync(0xffffffffu, mx1, 2));
        float sum0 = 0.f, sum1 = 0.f;
        #pragma unroll
        for (int nt = 0; nt < 26; nt++) {
            sc[nt][0] = __expf(sc[nt][0] - mx0);
            sc[nt][1] = __expf(sc[nt][1] - mx0);
            sc[nt][2] = __expf(sc[nt][2] - mx1);
            sc[nt][3] = __expf(sc[nt][3] - mx1);
            sum0 += sc[nt][0] + sc[nt][1];
            sum1 += sc[nt][2] + sc[nt][3];
        }
        sum0 += __shfl_xor_sync(0xffffffffu, sum0, 1);
        sum0 += __shfl_xor_sync(0xffffffffu, sum0, 2);
        sum1 += __shfl_xor_sync(0xffffffffu, sum1, 1);
        sum1 += __shfl_xor_sync(0xffffffffu, sum1, 2);
        float rv0 = 1.0f / sum0, rv1 = 1.0f / sum1;
        #pragma unroll
        for (int nt = 0; nt < 26; nt++) {
            sc[nt][0] *= rv0; sc[nt][1] *= rv0;
            sc[nt][2] *= rv1; sc[nt][3] *= rv1;
        }

        float oacc[8][4];
        #pragma unroll
        for (int i = 0; i < 8; i++)
            #pragma unroll
            for (int jx = 0; jx < 4; jx++) oacc[i][jx] = 0.f;

        for (int J = 0; J < 13; J++) {
            uint32_t pa_h[4];
            pa_h[0] = pack_bf16(sc[2*J][0],   sc[2*J][1]);
            pa_h[1] = pack_bf16(sc[2*J][2],   sc[2*J][3]);
            pa_h[2] = pack_bf16(sc[2*J+1][0], sc[2*J+1][1]);
            pa_h[3] = pack_bf16(sc[2*J+1][2], sc[2*J+1][3]);

            uint32_t vb = J * (16 * ALD) + voff;
            uint32_t bh[4][4];
            #pragma unroll
            for (int np = 0; np < 4; np++)
                ldsm4t(bh[np], svh + vb + np * 32);
            #pragma unroll
            for (int np = 0; np < 4; np++) {
                mma_bf16(oacc[2*np],   pa_h, bh[np][0], bh[np][1]);
                mma_bf16(oacc[2*np+1], pa_h, bh[np][2], bh[np][3]);
            }
        }

        int p0r = m0 + gr, p1r = m0 + gr + 8;
        #pragma unroll
        for (int nt2 = 0; nt2 < 8; nt2++) {
            int n = nt2 * 8 + qc;
            if (p0r < Pp)
                *(float2*)&Ob[(size_t)p0r * Dd + n] = make_float2(oacc[nt2][0], oacc[nt2][1]);
            if (p1r < Pp)
                *(float2*)&Ob[(size_t)p1r * Dd + n] = make_float2(oacc[nt2][2], oacc[nt2][3]);
        }
    }
}

// ---------------- launch ----------------
extern "C" void kernel_launch(void* const* d_in, const int* in_sizes, int n_in,
                              void* d_out, int out_size) {
    const float* x    = (const float*)d_in[0];
    const float* Wq   = (const float*)d_in[1];
    const float* bq   = (const float*)d_in[2];
    const float* Wk   = (const float*)d_in[3];
    const float* bk   = (const float*)d_in[4];
    const float* Wv   = (const float*)d_in[5];
    const float* bv   = (const float*)d_in[6];
    const float* in_a = (const float*)d_in[7];
    const float* in_b = (const float*)d_in[8];
    const float* at_a = (const float*)d_in[9];
    const float* at_b = (const float*)d_in[10];
    const float* ou_a = (const float*)d_in[11];
    const float* ou_b = (const float*)d_in[12];
    const float* Wt   = (const float*)d_in[13];
    const float* bt   = (const float*)d_in[14];
    const float* pos  = (const float*)d_in[15];
    const float* W1   = (const float*)d_in[16];
    const float* b1   = (const float*)d_in[17];
    const float* W2   = (const float*)d_in[18];
    const float* b2   = (const float*)d_in[19];

    float *pav, *pxres, *pbtsum, *pbqkv;
    __nv_bfloat16 *px2h, *pyh, *phh, *pwh, *pwl;
    cudaGetSymbolAddress((void**)&pav,  g_av);
    cudaGetSymbolAddress((void**)&pxres,g_xres);
    cudaGetSymbolAddress((void**)&pbtsum, g_btsum);
    cudaGetSymbolAddress((void**)&pbqkv, g_bqkv);
    cudaGetSymbolAddress((void**)&px2h, g_x2h);
    cudaGetSymbolAddress((void**)&pyh,  g_yh);
    cudaGetSymbolAddress((void**)&phh,  g_hh);
    cudaGetSymbolAddress((void**)&pwh,  w_hi);
    cudaGetSymbolAddress((void**)&pwl,  w_lo);

    cudaFuncSetAttribute(attn_mma_k, cudaFuncAttributeMaxDynamicSharedMemorySize,
                         ATT_SMEM);
    cudaFuncSetAttribute(gemm_mma_k, cudaFuncAttributeMaxDynamicSharedMemorySize,
                         GM_SMEM);

    // (0) pre1: LN(x) + QKV weight/bias convert
    pre1_k<<<4248, 256>>>(x, in_a, in_b, Wq, Wk, Wv, bq, bk, bv);
    // (1) merged QKV projection (mode 5), N = 1536
    dim3 gq(1536 / 128, (M1 + 127) / 128);
    gemm_mma_k<<<gq, 256, GM_SMEM>>>(px2h, pwh + OQ, pwl + OQ, pbqkv, nullptr,
                                     nullptr, nullptr, M1, 1536, Dd, 5);
    // (2) pre2: Wt/W1/W2 convert + btsum
    pre2_k<<<16386, 256>>>(Wt, W1, W2, bt);
    // (3) tensor-core attention -> g_av  (ncu capture slot)
    attn_mma_k<<<Bq * (Tt / TG) * Tt * Hh, 256, ATT_SMEM>>>();
    // (4) LN(av)+pos -> y hi
    ln_bf_k<<<ROWS_AV / 8, 256>>>(pav, at_a, at_b, pos, pyh, POSMOD);
    // (5) tc contraction (mode 1, L2-swizzled 1D grid)
    gemm_mma_k<<<296, 256, GM_SMEM>>>(pyh, pwh + OT, pwl + OT, pbtsum, x,
                                      pxres, nullptr, M1, Dd, Tt * Dd, 1);
    // (6) LN(xres) -> x2 hi
    ln_bf_k<<<M1 / 8, 256>>>(pxres, ou_a, ou_b, nullptr, px2h, 1);
    // (7) MLP1 (mode 2)
    dim3 g1(2 * Dd / 128, (M1 + 127) / 128);
    gemm_mma_k<<<g1, 256, GM_SMEM>>>(px2h, pwh + O1, pwl + O1, b1, nullptr,
                                     nullptr, phh, M1, 2 * Dd, Dd, 2);
    // (8) MLP2 (mode 3) -> d_out
    dim3 gtc(Dd / 128, (M1 + 127) / 128);
    gemm_mma_k<<<gtc, 256, GM_SMEM>>>(phh, pwh + O2, pwl + O2, b2, pxres,
                                      (float*)d_out, nullptr, M1, Dd, 2 * Dd, 3);
}

// round 17
// speedup vs baseline: 1.5467x; 1.0293x over previous
#include <cuda_runtime.h>
#include <cuda_bf16.h>
#include <math.h>
#include <stdint.h>

#define Bq 4
#define Tt 12
#define Pp 196
#define Dd 512
#define Hh 8
#define DHd 64
#define EPSV 1e-6f

#define M1 (Bq*Tt*Pp)            // 9408
#define ROWS_AV (Bq*Tt*Tt*Pp)    // 112896
#define POSMOD (Tt*Tt*Pp)        // 28224

#define OQ 0
#define OKo 262144
#define OV  524288
#define OT  786432
#define O1  3932160
#define O2  4456448
#define WTOT 4980736

// ---------------- scratch ----------------
__device__ float g_xres[M1*Dd];
__device__ float g_btsum[Dd];
__device__ float g_bqkv[3*Dd];
__device__ __nv_bfloat16 g_avh[(size_t)ROWS_AV*Dd];
__device__ __nv_bfloat16 g_x2h[M1*Dd];
__device__ __nv_bfloat16 g_qh[M1*Dd];
__device__ __nv_bfloat16 g_kh[M1*Dd];
__device__ __nv_bfloat16 g_vh[M1*Dd];
__device__ __nv_bfloat16 g_yh[(size_t)ROWS_AV*Dd];
__device__ __nv_bfloat16 g_hh[M1*2*Dd];
__device__ __nv_bfloat16 w_hi[WTOT], w_lo[WTOT];

// ---------------- helpers ----------------
__device__ __forceinline__ float gelu_exact(float x) {
    return 0.5f * x * (1.0f + erff(x * 0.70710678118654752f));
}
__device__ __forceinline__ uint32_t smem_u32(const void* p) {
    uint32_t a;
    asm("{ .reg .u64 t; cvta.to.shared.u64 t, %1; cvt.u32.u64 %0, t; }" : "=r"(a) : "l"(p));
    return a;
}
__device__ __forceinline__ void ldsm4(uint32_t* r, uint32_t a) {
    asm volatile("ldmatrix.sync.aligned.m8n8.x4.shared.b16 {%0,%1,%2,%3}, [%4];"
                 : "=r"(r[0]), "=r"(r[1]), "=r"(r[2]), "=r"(r[3]) : "r"(a));
}
__device__ __forceinline__ void ldsm4t(uint32_t* r, uint32_t a) {
    asm volatile("ldmatrix.sync.aligned.m8n8.x4.trans.shared.b16 {%0,%1,%2,%3}, [%4];"
                 : "=r"(r[0]), "=r"(r[1]), "=r"(r[2]), "=r"(r[3]) : "r"(a));
}
__device__ __forceinline__ void mma_bf16(float* c, const uint32_t* a, uint32_t b0, uint32_t b1) {
    asm volatile(
        "mma.sync.aligned.m16n8k16.row.col.f32.bf16.bf16.f32 "
        "{%0,%1,%2,%3}, {%4,%5,%6,%7}, {%8,%9}, {%0,%1,%2,%3};"
        : "+f"(c[0]), "+f"(c[1]), "+f"(c[2]), "+f"(c[3])
        : "r"(a[0]), "r"(a[1]), "r"(a[2]), "r"(a[3]), "r"(b0), "r"(b1));
}
__device__ __forceinline__ void cpa16(uint32_t s, const void* g) {
    asm volatile("cp.async.cg.shared.global [%0], [%1], 16;" :: "r"(s), "l"(g));
}
#define CPA_COMMIT() asm volatile("cp.async.commit_group;" ::: "memory")
#define CPA_WAIT(n)  asm volatile("cp.async.wait_group %0;" :: "n"(n) : "memory")

__device__ __forceinline__ uint32_t pack_bf16(float a, float b) {
    __nv_bfloat162 t = __floats2bfloat162_rn(a, b);
    return *(uint32_t*)&t;
}
__device__ __forceinline__ void split_store(__nv_bfloat16* hi, __nv_bfloat16* lo,
                                            size_t i, float v) {
    __nv_bfloat16 h = __float2bfloat16(v);
    hi[i] = h;
    lo[i] = __float2bfloat16(v - __bfloat162float(h));
}

// ---------------- LN row body (fp32 input, warp-per-row) ----------------
__device__ __forceinline__ void ln_row(const float* __restrict__ in,
                                       const float* __restrict__ al,
                                       const float* __restrict__ be,
                                       __nv_bfloat16* __restrict__ oh,
                                       int row, int lane) {
    const float* rp = in + (size_t)row * Dd;
    float4 v[4];
    float s = 0.f, sq = 0.f;
    #pragma unroll
    for (int j = 0; j < 4; j++) {
        v[j] = *(const float4*)&rp[lane * 4 + j * 128];
        s  += v[j].x + v[j].y + v[j].z + v[j].w;
        sq += v[j].x*v[j].x + v[j].y*v[j].y + v[j].z*v[j].z + v[j].w*v[j].w;
    }
    #pragma unroll
    for (int o = 16; o; o >>= 1) {
        s  += __shfl_xor_sync(0xffffffffu, s,  o);
        sq += __shfl_xor_sync(0xffffffffu, sq, o);
    }
    float mu  = s * (1.0f / Dd);
    float var = (sq - (float)Dd * mu * mu) * (1.0f / (Dd - 1));
    float inv = 1.0f / (sqrtf(fmaxf(var, 0.f)) + EPSV);

    #pragma unroll
    for (int j = 0; j < 4; j++) {
        int c = lane * 4 + j * 128;
        float4 a = *(const float4*)&al[c];
        float4 b = *(const float4*)&be[c];
        float o0 = a.x * (v[j].x - mu) * inv + b.x;
        float o1 = a.y * (v[j].y - mu) * inv + b.y;
        float o2 = a.z * (v[j].z - mu) * inv + b.z;
        float o3 = a.w * (v[j].w - mu) * inv + b.w;
        uint2 hv;
        hv.x = pack_bf16(o0, o1);
        hv.y = pack_bf16(o2, o3);
        *(uint2*)&oh[(size_t)row * Dd + c] = hv;
    }
}

// ---------------- LayerNorm standalone (fp32 in) ----------------
__global__ void ln_bf_k(const float* __restrict__ in,
                        const float* __restrict__ al,
                        const float* __restrict__ be,
                        __nv_bfloat16* __restrict__ oh) {
    int w = threadIdx.x >> 5, lane = threadIdx.x & 31;
    ln_row(in, al, be, oh, blockIdx.x * 8 + w, lane);
}

// ---------------- LayerNorm (bf16 input) + pos: for av ----------------
__global__ void ln_av_k(const float* __restrict__ al,
                        const float* __restrict__ be,
                        const float* __restrict__ pos) {
    int w = threadIdx.x >> 5, lane = threadIdx.x & 31;
    int row = blockIdx.x * 8 + w;
    const __nv_bfloat16* rp = g_avh + (size_t)row * Dd;
    float4 v[4];
    float s = 0.f, sq = 0.f;
    #pragma unroll
    for (int j = 0; j < 4; j++) {
        uint2 raw = *(const uint2*)&rp[lane * 4 + j * 128];
        __nv_bfloat162 p01 = *(__nv_bfloat162*)&raw.x;
        __nv_bfloat162 p23 = *(__nv_bfloat162*)&raw.y;
        v[j].x = __bfloat162float(p01.x);
        v[j].y = __bfloat162float(p01.y);
        v[j].z = __bfloat162float(p23.x);
        v[j].w = __bfloat162float(p23.y);
        s  += v[j].x + v[j].y + v[j].z + v[j].w;
        sq += v[j].x*v[j].x + v[j].y*v[j].y + v[j].z*v[j].z + v[j].w*v[j].w;
    }
    #pragma unroll
    for (int o = 16; o; o >>= 1) {
        s  += __shfl_xor_sync(0xffffffffu, s,  o);
        sq += __shfl_xor_sync(0xffffffffu, sq, o);
    }
    float mu  = s * (1.0f / Dd);
    float var = (sq - (float)Dd * mu * mu) * (1.0f / (Dd - 1));
    float inv = 1.0f / (sqrtf(fmaxf(var, 0.f)) + EPSV);
    const float* pp = pos + (size_t)(row % POSMOD) * Dd;

    #pragma unroll
    for (int j = 0; j < 4; j++) {
        int c = lane * 4 + j * 128;
        float4 a = *(const float4*)&al[c];
        float4 b = *(const float4*)&be[c];
        float4 p = *(const float4*)&pp[c];
        float o0 = a.x * (v[j].x - mu) * inv + b.x + p.x;
        float o1 = a.y * (v[j].y - mu) * inv + b.y + p.y;
        float o2 = a.z * (v[j].z - mu) * inv + b.z + p.z;
        float o3 = a.w * (v[j].w - mu) * inv + b.w + p.w;
        uint2 hv;
        hv.x = pack_bf16(o0, o1);
        hv.y = pack_bf16(o2, o3);
        *(uint2*)&g_yh[(size_t)row * Dd + c] = hv;
    }
}

// ---------------- pre1: LN(x) + QKV weight/bias convert ----------------
__global__ void pre1_k(const float* __restrict__ x,
                       const float* __restrict__ in_a, const float* __restrict__ in_b,
                       const float* __restrict__ Wq, const float* __restrict__ Wk,
                       const float* __restrict__ Wv,
                       const float* __restrict__ bq, const float* __restrict__ bk,
                       const float* __restrict__ bv) {
    int bid = blockIdx.x, tid = threadIdx.x;
    if (bid < 1176) {
        int w = tid >> 5, lane = tid & 31;
        ln_row(x, in_a, in_b, g_x2h, bid * 8 + w, lane);
    } else {
        int i = (bid - 1176) * 256 + tid;
        if (i < 3 * Dd)
            g_bqkv[i] = (i < Dd) ? bq[i] : (i < 2 * Dd) ? bk[i - Dd] : bv[i - 2 * Dd];
        if (i < 786432) {
            int seg = i >> 18, off = i & 262143;
            float v = (seg == 0) ? Wq[off] : (seg == 1) ? Wk[off] : Wv[off];
            split_store(w_hi, w_lo, i, v);
        }
    }
}

// ---------------- pre2: Wt/W1/W2 convert + btsum ----------
__global__ void pre2_k(const float* __restrict__ Wt, const float* __restrict__ W1,
                       const float* __restrict__ W2, const float* __restrict__ bt) {
    int bid = blockIdx.x, tid = threadIdx.x;
    if (bid < 16384) {
        int i = bid * 256 + tid;
        float v; int di;
        if (i < 3145728)      { v = Wt[i];            di = OT + i; }
        else if (i < 3670016) { v = W1[i - 3145728];  di = O1 + (i - 3145728); }
        else                  { v = W2[i - 3670016];  di = O2 + (i - 3670016); }
        split_store(w_hi, w_lo, di, v);
    } else {
        int e = (bid - 16384) * 256 + tid;
        if (e < Dd) {
            float s = 0.f;
            #pragma unroll
            for (int u = 0; u < Tt; u++) s += bt[u * Dd + e];
            g_btsum[e] = s;
        }
    }
}

// ================= mma.sync GEMM: A bf16-hi, B bf16x2 (hi+lo) ======================
#define LDP 80
#define TILE_B (128*LDP)
#define STAGE_B (3*TILE_B)
#define GM_SMEM (2*STAGE_B)

__global__ void __launch_bounds__(256, 2) gemm_mma_k(
    const __nv_bfloat16* __restrict__ Ahi,
    const __nv_bfloat16* __restrict__ Bhi, const __nv_bfloat16* __restrict__ Blo,
    const float* __restrict__ bias, const float* __restrict__ res,
    float* __restrict__ Cf, __nv_bfloat16* __restrict__ Chi,
    int M, int N, int K, int mode)
{
    extern __shared__ char smc[];
    int tid = threadIdx.x;
    int wid = tid >> 5, lane = tid & 31;
    int bm, bn;
    if (mode == 1) {
        int bid2 = blockIdx.x;
        int g = bid2 >> 5, r = bid2 & 31;
        int bmi, bni;
        if (g < 9) { bmi = g * 8 + (r & 7); bni = r >> 3; }
        else       { bmi = 72 + (r & 1);    bni = r >> 1; }
        bm = bmi * 128; bn = bni * 128;
    } else {
        bm = blockIdx.y * 128; bn = blockIdx.x * 128;
    }
    int wm = (wid >> 2) * 64;
    int wn = (wid & 3) * 32;

    int lrow = tid >> 1;
    int lhalf = tid & 1;
    int am = min(bm + lrow, M - 1);
    size_t abase;
    if (mode == 1) {
        int b_ = am / (Tt * Pp), r_ = am % (Tt * Pp);
        int t_ = r_ / Pp, p_ = r_ % Pp;
        abase = ((size_t)(b_ * (Tt * Tt) + t_ * Tt) * Pp + p_) * Dd;
    } else {
        abase = (size_t)am * K;
    }
    int brow = bn + lrow;
    uint32_t smrow = lrow * LDP;

    int NC = K / 32;

    auto load_stage = [&](int buf, int c) {
        size_t aoff, boff;
        if (mode == 1) {
            int u = c >> 4, d0 = (c & 15) * 32;
            aoff = abase + (size_t)u * (Pp * Dd) + d0;
            boff = (size_t)u * (Dd * Dd) + (size_t)brow * Dd + d0;
        } else {
            aoff = abase + c * 32;
            boff = (size_t)brow * K + c * 32;
        }
        uint32_t sb = smem_u32(smc) + buf * STAGE_B + smrow;
        #pragma unroll
        for (int i = 0; i < 2; i++) {
            int colk = lhalf * 16 + i * 8;
            uint32_t so = sb + colk * 2;
            cpa16(so,              Ahi + aoff + colk);
            cpa16(so + TILE_B,     Bhi + boff + colk);
            cpa16(so + 2*TILE_B,   Blo + boff + colk);
        }
    };

    int sel = lane >> 3, lr = lane & 7;
    int a_m = wm + (sel & 1) * 8 + lr;
    int b_n = wn + (sel >> 1) * 8 + lr;
    uint32_t smb = smem_u32(smc);
    uint32_t aoffB = a_m * LDP + (sel >> 1) * 16;
    uint32_t boffB = b_n * LDP + (sel & 1) * 16;

    float acc[4][4][4] = {};

    load_stage(0, 0);
    CPA_COMMIT();

    for (int c = 0; c < NC; c++) {
        int buf = c & 1;
        if (c + 1 < NC) {
            load_stage(buf ^ 1, c + 1);
            CPA_COMMIT();
            CPA_WAIT(1);
        } else {
            CPA_WAIT(0);
        }
        __syncthreads();

        uint32_t base = smb + buf * STAGE_B;
        uint32_t aHb = base + aoffB;
        uint32_t bHb = base + TILE_B + boffB;
        uint32_t bLb = base + 2*TILE_B + boffB;

        #pragma unroll
        for (int kk = 0; kk < 2; kk++) {
            uint32_t ko = kk * 32;
            uint32_t bH[2][4], bL[2][4];
            #pragma unroll
            for (int nt2 = 0; nt2 < 2; nt2++) {
                ldsm4(bH[nt2], bHb + nt2 * (16 * LDP) + ko);
                ldsm4(bL[nt2], bLb + nt2 * (16 * LDP) + ko);
            }
            #pragma unroll
            for (int mt = 0; mt < 4; mt++) {
                uint32_t aH[4];
                ldsm4(aH, aHb + mt * (16 * LDP) + ko);
                #pragma unroll
                for (int nt = 0; nt < 4; nt++) {
                    int s2 = nt >> 1, pp = (nt & 1) * 2;
                    mma_bf16(acc[mt][nt], aH, bH[s2][pp], bH[s2][pp+1]);
                }
                #pragma unroll
                for (int nt = 0; nt < 4; nt++) {
                    int s2 = nt >> 1, pp = (nt & 1) * 2;
                    mma_bf16(acc[mt][nt], aH, bL[s2][pp], bL[s2][pp+1]);
                }
            }
        }
        __syncthreads();
    }

    int qrow = lane >> 2;
    int qcol = (lane & 3) * 2;
    #pragma unroll
    for (int mt = 0; mt < 4; mt++) {
        #pragma unroll
        for (int nt = 0; nt < 4; nt++) {
            float* cc = acc[mt][nt];
            int n0 = bn + wn + nt * 8 + qcol;
            float b0 = bias[n0], b1 = bias[n0 + 1];
            #pragma unroll
            for (int hrow = 0; hrow < 2; hrow++) {
                int m = bm + wm + mt * 16 + qrow + hrow * 8;
                if (m >= M) continue;
                float a0 = cc[hrow * 2 + 0];
                float a1 = cc[hrow * 2 + 1];
                float v0, v1;
                if (mode == 0) {
                    size_t off = (size_t)m * N + n0;
                    v0 = a0 + b0; v1 = a1 + b1;
                    *(float2*)&Cf[off] = make_float2(v0, v1);
                } else if (mode == 1) {
                    size_t off = (size_t)m * N + n0;
                    float2 r = *(const float2*)&res[off];
                    v0 = r.x + gelu_exact(a0 * (1.0f / Tt) + b0);
                    v1 = r.y + gelu_exact(a1 * (1.0f / Tt) + b1);
                    *(float2*)&Cf[off] = make_float2(v0, v1);
                } else if (mode == 3) {
                    size_t off = (size_t)m * N + n0;
                    float2 r = *(const float2*)&res[off];
                    v0 = r.x + gelu_exact(a0 + b0);
                    v1 = r.y + gelu_exact(a1 + b1);
                    *(float2*)&Cf[off] = make_float2(v0, v1);
                } else if (mode == 5) {
                    int seg = n0 >> 9, nn = n0 & 511;
                    float g0 = a0 + b0, g1 = a1 + b1;
                    size_t off = (size_t)m * Dd + nn;
                    __nv_bfloat16* dh = (seg == 0) ? g_qh : (seg == 1) ? g_kh : g_vh;
                    *(uint32_t*)(dh + off) = pack_bf16(g0, g1);
                } else { // mode 2
                    size_t off = (size_t)m * N + n0;
                    float g0 = gelu_exact(a0 + b0);
                    float g1 = gelu_exact(a1 + b1);
                    *(uint32_t*)(Chi + off) = pack_bf16(g0, g1);
                }
            }
        }
    }
}

// ================= tensor-core attention — pure bf16, 2 blocks/SM =====
#define AKR 208
#define ALD 144
#define ASM_ONE (AKR*ALD)
#define ATT_SMEM (2*ASM_ONE)
#define TG 4

__global__ void __launch_bounds__(128, 2) attn_mma_k() {
    int bid = blockIdx.x;
    int h = bid & 7;
    int u = (bid >> 3) % Tt;
    int tg = (bid / (8 * Tt)) % (Tt / TG);
    int b = bid / (8 * Tt * (Tt / TG));

    extern __shared__ char smb_[];
    uint32_t skh = smem_u32(smb_);
    uint32_t svh = skh + ASM_ONE;

    int tid = threadIdx.x;
    int w = tid >> 5, lane = tid & 31;

    size_t kvbase = ((size_t)(b * Tt + u) * Pp) * Dd + h * DHd;

    for (int idx = tid; idx < AKR * 8; idx += 128) {
        int row = idx >> 3, seg = idx & 7;
        uint4 kh4 = make_uint4(0,0,0,0), vh4 = kh4;
        if (row < Pp) {
            size_t g = kvbase + (size_t)row * Dd + seg * 8;
            kh4 = *(const uint4*)&g_kh[g];
            vh4 = *(const uint4*)&g_vh[g];
        }
        uint32_t so = row * ALD + seg * 16;
        *(uint4*)(smb_ + so) = kh4;
        *(uint4*)(smb_ + ASM_ONE + so) = vh4;
    }
    __syncthreads();

    int gr = lane >> 2, qc = (lane & 3) * 2;
    int sel = lane >> 3, lr = lane & 7;
    uint32_t koff = ((sel >> 1) * 8 + lr) * ALD + (sel & 1) * 16;
    uint32_t voff = ((sel & 1) * 8 + lr) * ALD + (sel >> 1) * 16;

    for (int tau = w; tau < 13 * TG; tau += 4) {
        int tl = tau / 13, mt = tau % 13;
        int t = tg * TG + tl;
        size_t qbase = ((size_t)(b * Tt + t) * Pp) * Dd + h * DHd;
        __nv_bfloat16* Ob = g_avh + ((size_t)((b * Tt + t) * Tt + u) * Pp) * Dd + h * DHd;

        int m0 = mt * 16;
        int r0 = min(m0 + gr, Pp - 1);
        int r1 = min(m0 + gr + 8, Pp - 1);

        uint32_t qa_h[4][4];
        #pragma unroll
        for (int J = 0; J < 4; J++) {
            int c0 = J * 16 + qc;
            qa_h[J][0] = *(const uint32_t*)&g_qh[qbase + (size_t)r0 * Dd + c0];
            qa_h[J][1] = *(const uint32_t*)&g_qh[qbase + (size_t)r1 * Dd + c0];
            qa_h[J][2] = *(const uint32_t*)&g_qh[qbase + (size_t)r0 * Dd + c0 + 8];
            qa_h[J][3] = *(const uint32_t*)&g_qh[qbase + (size_t)r1 * Dd + c0 + 8];
        }

        float sc[26][4];
        #pragma unroll
        for (int nt = 0; nt < 26; nt++)
            #pragma unroll
            for (int i = 0; i < 4; i++) sc[nt][i] = 0.f;

        #pragma unroll
        for (int J = 0; J < 4; J++) {
            for (int ntp = 0; ntp < 12; ntp += 2) {
                uint32_t kb0 = ntp * (16 * ALD) + koff + J * 32;
                uint32_t kb1 = kb0 + 16 * ALD;
                uint32_t bh0[4], bh1[4];
                ldsm4(bh0, skh + kb0);
                ldsm4(bh1, skh + kb1);
                mma_bf16(sc[2*ntp],   qa_h[J], bh0[0], bh0[1]);
                mma_bf16(sc[2*ntp+1], qa_h[J], bh0[2], bh0[3]);
                mma_bf16(sc[2*ntp+2], qa_h[J], bh1[0], bh1[1]);
                mma_bf16(sc[2*ntp+3], qa_h[J], bh1[2], bh1[3]);
            }
            {
                uint32_t kb = 12 * (16 * ALD) + koff + J * 32;
                uint32_t bh[4];
                ldsm4(bh, skh + kb);
                mma_bf16(sc[24], qa_h[J], bh[0], bh[1]);
                mma_bf16(sc[25], qa_h[J], bh[2], bh[3]);
            }
        }

        float mx0 = -1e30f, mx1 = -1e30f;
        #pragma unroll
        for (int nt = 0; nt < 26; nt++) {
            int n0 = nt * 8 + qc;
            if (n0 >= Pp) {
                sc[nt][0] = sc[nt][1] = sc[nt][2] = sc[nt][3] = -1e30f;
            } else {
                sc[nt][0] *= 0.125f; sc[nt][1] *= 0.125f;
                sc[nt][2] *= 0.125f; sc[nt][3] *= 0.125f;
            }
            mx0 = fmaxf(mx0, fmaxf(sc[nt][0], sc[nt][1]));
            mx1 = fmaxf(mx1, fmaxf(sc[nt][2], sc[nt][3]));
        }
        mx0 = fmaxf(mx0, __shfl_xor_sync(0xffffffffu, mx0, 1));
        mx0 = fmaxf(mx0, __shfl_xor_sync(0xffffffffu, mx0, 2));
        mx1 = fmaxf(mx1, __shfl_xor_sync(0xffffffffu, mx1, 1));
        mx1 = fmaxf(mx1, __shfl_xor_sync(0xffffffffu, mx1, 2));
        float sum0 = 0.f, sum1 = 0.f;
        #pragma unroll
        for (int nt = 0; nt < 26; nt++) {
            sc[nt][0] = __expf(sc[nt][0] - mx0);
            sc[nt][1] = __expf(sc[nt][1] - mx0);
            sc[nt][2] = __expf(sc[nt][2] - mx1);
            sc[nt][3] = __expf(sc[nt][3] - mx1);
            sum0 += sc[nt][0] + sc[nt][1];
            sum1 += sc[nt][2] + sc[nt][3];
        }
        sum0 += __shfl_xor_sync(0xffffffffu, sum0, 1);
        sum0 += __shfl_xor_sync(0xffffffffu, sum0, 2);
        sum1 += __shfl_xor_sync(0xffffffffu, sum1, 1);
        sum1 += __shfl_xor_sync(0xffffffffu, sum1, 2);
        float rv0 = 1.0f / sum0, rv1 = 1.0f / sum1;
        #pragma unroll
        for (int nt = 0; nt < 26; nt++) {
            sc[nt][0] *= rv0; sc[nt][1] *= rv0;
            sc[nt][2] *= rv1; sc[nt][3] *= rv1;
        }

        float oacc[8][4];
        #pragma unroll
        for (int i = 0; i < 8; i++)
            #pragma unroll
            for (int jx = 0; jx < 4; jx++) oacc[i][jx] = 0.f;

        for (int J = 0; J < 13; J++) {
            uint32_t pa_h[4];
            pa_h[0] = pack_bf16(sc[2*J][0],   sc[2*J][1]);
            pa_h[1] = pack_bf16(sc[2*J][2],   sc[2*J][3]);
            pa_h[2] = pack_bf16(sc[2*J+1][0], sc[2*J+1][1]);
            pa_h[3] = pack_bf16(sc[2*J+1][2], sc[2*J+1][3]);

            uint32_t vb = J * (16 * ALD) + voff;
            uint32_t bh[4][4];
            #pragma unroll
            for (int np = 0; np < 4; np++)
                ldsm4t(bh[np], svh + vb + np * 32);
            #pragma unroll
            for (int np = 0; np < 4; np++) {
                mma_bf16(oacc[2*np],   pa_h, bh[np][0], bh[np][1]);
                mma_bf16(oacc[2*np+1], pa_h, bh[np][2], bh[np][3]);
            }
        }

        int p0r = m0 + gr, p1r = m0 + gr + 8;
        #pragma unroll
        for (int nt2 = 0; nt2 < 8; nt2++) {
            int n = nt2 * 8 + qc;
            if (p0r < Pp)
                *(uint32_t*)&Ob[(size_t)p0r * Dd + n] = pack_bf16(oacc[nt2][0], oacc[nt2][1]);
            if (p1r < Pp)
                *(uint32_t*)&Ob[(size_t)p1r * Dd + n] = pack_bf16(oacc[nt2][2], oacc[nt2][3]);
        }
    }
}

// ---------------- launch ----------------
extern "C" void kernel_launch(void* const* d_in, const int* in_sizes, int n_in,
                              void* d_out, int out_size) {
    const float* x    = (const float*)d_in[0];
    const float* Wq   = (const float*)d_in[1];
    const float* bq   = (const float*)d_in[2];
    const float* Wk   = (const float*)d_in[3];
    const float* bk   = (const float*)d_in[4];
    const float* Wv   = (const float*)d_in[5];
    const float* bv   = (const float*)d_in[6];
    const float* in_a = (const float*)d_in[7];
    const float* in_b = (const float*)d_in[8];
    const float* at_a = (const float*)d_in[9];
    const float* at_b = (const float*)d_in[10];
    const float* ou_a = (const float*)d_in[11];
    const float* ou_b = (const float*)d_in[12];
    const float* Wt   = (const float*)d_in[13];
    const float* bt   = (const float*)d_in[14];
    const float* pos  = (const float*)d_in[15];
    const float* W1   = (const float*)d_in[16];
    const float* b1   = (const float*)d_in[17];
    const float* W2   = (const float*)d_in[18];
    const float* b2   = (const float*)d_in[19];

    float *pxres, *pbtsum, *pbqkv;
    __nv_bfloat16 *px2h, *pyh, *phh, *pwh, *pwl;
    cudaGetSymbolAddress((void**)&pxres,g_xres);
    cudaGetSymbolAddress((void**)&pbtsum, g_btsum);
    cudaGetSymbolAddress((void**)&pbqkv, g_bqkv);
    cudaGetSymbolAddress((void**)&px2h, g_x2h);
    cudaGetSymbolAddress((void**)&pyh,  g_yh);
    cudaGetSymbolAddress((void**)&phh,  g_hh);
    cudaGetSymbolAddress((void**)&pwh,  w_hi);
    cudaGetSymbolAddress((void**)&pwl,  w_lo);

    cudaFuncSetAttribute(attn_mma_k, cudaFuncAttributeMaxDynamicSharedMemorySize,
                         ATT_SMEM);
    cudaFuncSetAttribute(gemm_mma_k, cudaFuncAttributeMaxDynamicSharedMemorySize,
                         GM_SMEM);

    // (0) pre1: LN(x) + QKV weight/bias convert
    pre1_k<<<4248, 256>>>(x, in_a, in_b, Wq, Wk, Wv, bq, bk, bv);
    // (1) merged QKV projection (mode 5), N = 1536
    dim3 gq(1536 / 128, (M1 + 127) / 128);
    gemm_mma_k<<<gq, 256, GM_SMEM>>>(px2h, pwh + OQ, pwl + OQ, pbqkv, nullptr,
                                     nullptr, nullptr, M1, 1536, Dd, 5);
    // (2) pre2: Wt/W1/W2 convert + btsum
    pre2_k<<<16386, 256>>>(Wt, W1, W2, bt);
    // (3) tensor-core attention -> g_avh (bf16)  (ncu capture slot)
    attn_mma_k<<<Bq * (Tt / TG) * Tt * Hh, 128, ATT_SMEM>>>();
    // (4) LN(av)+pos -> y hi (bf16 in)
    ln_av_k<<<ROWS_AV / 8, 256>>>(at_a, at_b, pos);
    // (5) tc contraction (mode 1, L2-swizzled 1D grid)
    gemm_mma_k<<<296, 256, GM_SMEM>>>(pyh, pwh + OT, pwl + OT, pbtsum, x,
                                      pxres, nullptr, M1, Dd, Tt * Dd, 1);
    // (6) LN(xres) -> x2 hi
    ln_bf_k<<<M1 / 8, 256>>>(pxres, ou_a, ou_b, px2h);
    // (7) MLP1 (mode 2)
    dim3 g1(2 * Dd / 128, (M1 + 127) / 128);
    gemm_mma_k<<<g1, 256, GM_SMEM>>>(px2h, pwh + O1, pwl + O1, b1, nullptr,
                                     nullptr, phh, M1, 2 * Dd, Dd, 2);
    // (8) MLP2 (mode 3) -> d_out
    dim3 gtc(Dd / 128, (M1 + 127) / 128);
    gemm_mma_k<<<gtc, 256, GM_SMEM>>>(phh, pwh + O2, pwl + O2, b2, pxres,
                                      (float*)d_out, nullptr, M1, Dd, 2 * Dd, 3);
}